// round 7
// baseline (speedup 1.0000x reference)
#include <cuda_runtime.h>
#include <math.h>

#define NRES 768
#define MSAD 384
#define NH 12
#define PAIRD 128
#define OUTD 384
#define PROJ 1152
#define FINALD 2112

typedef unsigned long long ull;

// ---------------- f32x2 helpers (Blackwell packed fp32) ---------------------
__device__ __forceinline__ ull pk2(float v) {
    ull r; asm("mov.b64 %0, {%1, %1};" : "=l"(r) : "f"(v)); return r;
}
__device__ __forceinline__ ull pk2two(float lo, float hi) {
    ull r; asm("mov.b64 %0, {%1, %2};" : "=l"(r) : "f"(lo), "f"(hi)); return r;
}
__device__ __forceinline__ void fma2(ull& d, ull a, ull b) {
    asm("fma.rn.f32x2 %0, %1, %2, %0;" : "+l"(d) : "l"(a), "l"(b));
}
__device__ __forceinline__ float2 upk(ull v) {
    float2 r; asm("mov.b64 {%0, %1}, %2;" : "=f"(r.x), "=f"(r.y) : "l"(v)); return r;
}
// ---------------- cp.async helpers ------------------------------------------
__device__ __forceinline__ void cp16(void* dst, const void* src) {
    unsigned d = (unsigned)__cvta_generic_to_shared(dst);
    asm volatile("cp.async.cg.shared.global [%0], [%1], 16;" :: "r"(d), "l"(src));
}
__device__ __forceinline__ void cp_commit() {
    asm volatile("cp.async.commit_group;" ::: "memory");
}
__device__ __forceinline__ void cp_wait2() {
    asm volatile("cp.async.wait_group 2;" ::: "memory");
}

// ---------------- scratch (device globals; no allocation allowed) ----------
__device__ float g_wcat[MSAD * PROJ];
__device__ float g_bcat[PROJ];
__device__ float g_pw[NH];
__device__ float g_proj[NRES * PROJ];
__device__ float g_qpack[NH * NRES * 28];
__device__ float g_kpack[NH * NRES * 32];
__device__ float g_vpack2[NH * NRES * 40];
__device__ float g_logits[NH * NRES * NRES]; // raw logits (k2) -> attn (k4a)
__device__ float g_final[NRES * FINALD];
__device__ float g_part[3][NRES * OUTD];

// ---------------- K0 --------------------------------------------------------
__global__ void k0_prep(const float* __restrict__ qw, const float* __restrict__ qb,
                        const float* __restrict__ kvw, const float* __restrict__ kvb,
                        const float* __restrict__ qpw, const float* __restrict__ qpb,
                        const float* __restrict__ kvpw, const float* __restrict__ kvpb,
                        const float* __restrict__ tpw) {
    int idx = blockIdx.x * blockDim.x + threadIdx.x;
    if (idx < MSAD * PROJ) {
        int k = idx / PROJ, o = idx % PROJ;
        float v;
        if (o < 192)      v = qw[k * 192 + o];
        else if (o < 576) v = kvw[k * 384 + (o - 192)];
        else if (o < 720) v = qpw[k * 144 + (o - 576)];
        else              v = kvpw[k * 432 + (o - 720)];
        g_wcat[idx] = v;
    }
    if (idx < PROJ) {
        float b;
        if (idx < 192)      b = qb[idx];
        else if (idx < 576) b = kvb[idx - 192];
        else if (idx < 720) b = qpb[idx - 576];
        else                b = kvpb[idx - 720];
        g_bcat[idx] = b;
    }
    if (idx < NH) {
        float x = tpw[idx];
        float sp = (x > 20.f) ? x : log1pf(__expf(x));
        g_pw[idx] = sp * 0.13608276348795434f; // sqrt(1/54)
    }
}

// ---------------- K1a: projection GEMM 768x1152x384 (f32x2) -----------------
__global__ __launch_bounds__(256) void k1a_gemm(const float* __restrict__ in1d) {
    __shared__ float sA[32][65];
    __shared__ ull sB2[32][32];
    int tid = threadIdx.x;
    int tx = tid & 15, ty = tid >> 4;
    int m0 = blockIdx.y * 64, n0 = blockIdx.x * 64;
    ull acc[4][2] = {};
    for (int k0 = 0; k0 < MSAD; k0 += 32) {
        for (int idx = tid; idx < 64 * 32; idx += 256) {
            int m = idx >> 5, kk = idx & 31;
            sA[kk][m] = in1d[(m0 + m) * MSAD + k0 + kk];
        }
        for (int idx = tid; idx < 32 * 32; idx += 256) {
            int kk = idx >> 5, op = idx & 31;
            float2 w = *(const float2*)(g_wcat + (size_t)(k0 + kk) * PROJ + n0 + op * 2);
            sB2[kk][op] = pk2two(w.x, w.y);
        }
        __syncthreads();
#pragma unroll
        for (int kk = 0; kk < 32; kk++) {
            ulonglong2 b01 = *(const ulonglong2*)&sB2[kk][tx * 2];
#pragma unroll
            for (int r = 0; r < 4; r++) {
                ull a2 = pk2(sA[kk][ty * 4 + r]);
                fma2(acc[r][0], a2, b01.x);
                fma2(acc[r][1], a2, b01.y);
            }
        }
        __syncthreads();
    }
#pragma unroll
    for (int r = 0; r < 4; r++) {
        int m = m0 + ty * 4 + r, o = n0 + tx * 4;
        float2 lo = upk(acc[r][0]), hi = upk(acc[r][1]);
        g_proj[(size_t)m * PROJ + o + 0] = lo.x + g_bcat[o + 0];
        g_proj[(size_t)m * PROJ + o + 1] = lo.y + g_bcat[o + 1];
        g_proj[(size_t)m * PROJ + o + 2] = hi.x + g_bcat[o + 2];
        g_proj[(size_t)m * PROJ + o + 3] = hi.y + g_bcat[o + 3];
    }
}

// ---------------- K1b: apply rotations, pack q/k/v --------------------------
__global__ __launch_bounds__(256) void k1b_pack(const float* __restrict__ rot,
                                                const float* __restrict__ trans) {
    __shared__ float sp[PROJ];
    __shared__ float srot[9], strans[3], spw[12];
    __shared__ float sg[192 * 3];
    int n = blockIdx.x, tid = threadIdx.x;
    for (int t = tid; t < PROJ; t += 256) sp[t] = g_proj[n * PROJ + t];
    if (tid < 9) srot[tid] = rot[n * 9 + tid];
    if (tid < 3) strans[tid] = trans[n * 3 + tid];
    if (tid < 12) spw[tid] = g_pw[tid];
    __syncthreads();

    if (tid < 192) {
        int h = tid >> 4, d = tid & 15;
        g_qpack[(h * NRES + n) * 28 + d] = sp[tid] * 0.14433756729740643f; // 1/sqrt(48)
    }
    for (int t = tid; t < 384; t += 256) {
        int h = t >> 5, d = t & 31;
        if (d < 16) g_kpack[(h * NRES + n) * 32 + d] = sp[192 + t];
        else        g_vpack2[((size_t)h * NRES + n) * 40 + (d - 16)] = sp[192 + t];
    }
    if (tid < 192) {
        float l0, l1, l2;
        if (tid < 48) { l0 = sp[576 + tid]; l1 = sp[576 + 48 + tid]; l2 = sp[576 + 96 + tid]; }
        else { int vs = tid - 48; l0 = sp[720 + vs]; l1 = sp[720 + 144 + vs]; l2 = sp[720 + 288 + vs]; }
#pragma unroll
        for (int c = 0; c < 3; c++)
            sg[tid * 3 + c] = srot[c * 3 + 0] * l0 + srot[c * 3 + 1] * l1 + srot[c * 3 + 2] * l2 + strans[c];
    }
    __syncthreads();
    if (tid < 48) {
        int h = tid >> 2, p = tid & 3;
        float pw = spw[h];
#pragma unroll
        for (int c = 0; c < 3; c++)
            g_qpack[(h * NRES + n) * 28 + 16 + p * 3 + c] = pw * sg[tid * 3 + c];
    } else if (tid < 192) {
        int vs = tid - 48, h = vs / 12, s = vs % 12;
        if (s < 4) {
#pragma unroll
            for (int c = 0; c < 3; c++)
                g_kpack[(h * NRES + n) * 32 + 16 + s * 3 + c] = sg[tid * 3 + c];
        } else {
#pragma unroll
            for (int c = 0; c < 3; c++)
                g_vpack2[((size_t)h * NRES + n) * 40 + 16 + (s - 4) * 3 + c] = sg[tid * 3 + c];
        }
    }
    if (tid >= 192 && tid < 204) {
        int h = tid - 192;
        float s2 = 0.f;
        for (int s = 0; s < 4; s++)
            for (int c = 0; c < 3; c++) {
                float v = sg[(48 + h * 12 + s) * 3 + c];
                s2 += v * v;
            }
        g_kpack[(h * NRES + n) * 32 + 28] = -0.5f * spw[h] * s2;
    }
}

// ---------------- K2: a2d + qk logits -> RAW logits --------------------------
// 128 threads, block = (i, 128-wide j chunk). grid 768*6 = 4608.
// smem: sA float[128*33] @0 (16896), sw2 ull[768] @16896 (6144),
//       sq2 ull[168] @23040 (1344), sb float[12] @24384
#define K2_SMEM 24432
__global__ __launch_bounds__(128) void k2_logits(const float* __restrict__ in2d,
                                                 const float* __restrict__ w2d,
                                                 const float* __restrict__ b2d) {
    extern __shared__ char smraw[];
    float* sA  = (float*)smraw;
    ull*   sw2 = (ull*)(smraw + 16896);
    ull*   sq2 = (ull*)(smraw + 23040);
    float* sb  = (float*)(smraw + 24384);
    int tid = threadIdx.x;
    int i  = blockIdx.x / 6;
    int j0 = (blockIdx.x % 6) * 128;

    for (int f = tid; f < 128 * 6; f += 128) {
        int c = f / 6, hp = f % 6;
        float2 w = *(const float2*)(w2d + c * 12 + hp * 2);
        sw2[f] = pk2two(w.x, w.y);
    }
    for (int f = tid; f < 12 * 14; f += 128) {
        int h = f / 14, dp = f % 14;
        const float* qp = g_qpack + ((size_t)h * NRES + i) * 28 + dp * 2;
        sq2[f] = pk2two(qp[0], qp[1]);
    }
    if (tid < 12) sb[tid] = b2d[tid];

    const float* src = in2d + ((size_t)i * NRES + j0) * PAIRD;
    ull acc[6] = {};
#pragma unroll
    for (int ck = 0; ck < 4; ck++) {
        __syncthreads();
        for (int f = tid; f < 1024; f += 128) {
            int r = f >> 3, c4 = f & 7;
            float4 v = __ldg((const float4*)(src + (size_t)r * PAIRD + ck * 32) + c4);
            float* d = &sA[r * 33 + c4 * 4];
            d[0] = v.x; d[1] = v.y; d[2] = v.z; d[3] = v.w;
        }
        __syncthreads();
        const float* A = sA + tid * 33;
#pragma unroll
        for (int k = 0; k < 32; k++) {
            ull a2 = pk2(A[k]);
            const ull* w = &sw2[(ck * 32 + k) * 6];
            ulonglong2 w01 = *(const ulonglong2*)(w + 0);
            ulonglong2 w23 = *(const ulonglong2*)(w + 2);
            ulonglong2 w45 = *(const ulonglong2*)(w + 4);
            fma2(acc[0], a2, w01.x); fma2(acc[1], a2, w01.y);
            fma2(acc[2], a2, w23.x); fma2(acc[3], a2, w23.y);
            fma2(acc[4], a2, w45.x); fma2(acc[5], a2, w45.y);
        }
    }
    float res[12];
#pragma unroll
    for (int hp = 0; hp < 6; hp++) {
        float2 v = upk(acc[hp]);
        res[2 * hp] = v.x; res[2 * hp + 1] = v.y;
    }
    int j = j0 + tid;
#pragma unroll
    for (int h = 0; h < 12; h++) {
        const ull* kp2 = (const ull*)(g_kpack + ((size_t)h * NRES + j) * 32);
        ull wacc = 0;
#pragma unroll
        for (int dp = 0; dp < 14; dp++)
            fma2(wacc, sq2[h * 14 + dp], __ldg(&kp2[dp]));
        float2 t = upk(wacc);
        g_logits[((size_t)h * NRES + i) * NRES + j] =
            t.x + t.y + __ldg((const float*)kp2 + 28)
            + (res[h] + sb[h]) * 0.5773502691896258f;
    }
}

// ---------------- K4a: softmax + a_over_2d (cp.async 4-deep) ----------------
// One block per query row i, 256 threads.
// smem: sattn float[12*768] @0 (36864), sbuf float[4][16*128] @36864 (32768)
#define K4A_SMEM 69632
__global__ __launch_bounds__(256) void k4a_aover(const float* __restrict__ in2d) {
    extern __shared__ char smraw[];
    float* sattn = (float*)smraw;
    float* sbuf  = (float*)(smraw + 36864);
    int i = blockIdx.x, tid = threadIdx.x;

    // 1) load raw logits
    for (int f = tid; f < 2304; f += 256) {
        int h = f / 192, q = f % 192;
        ((float4*)(sattn + h * NRES))[q] =
            __ldg((const float4*)(g_logits + ((size_t)h * NRES + i) * NRES) + q);
    }
    __syncthreads();

    // 2) softmax (warp per head)
    int w = tid >> 5, lane = tid & 31;
    for (int hh = w; hh < 12; hh += 8) {
        float vals[24];
        float m = -1e30f;
#pragma unroll
        for (int t = 0; t < 24; t++) {
            vals[t] = sattn[hh * NRES + t * 32 + lane];
            m = fmaxf(m, vals[t]);
        }
#pragma unroll
        for (int o = 16; o > 0; o >>= 1) m = fmaxf(m, __shfl_xor_sync(~0u, m, o));
        float s = 0.f;
#pragma unroll
        for (int t = 0; t < 24; t++) {
            float e = __expf(vals[t] - m);
            vals[t] = e; s += e;
        }
#pragma unroll
        for (int o = 16; o > 0; o >>= 1) s += __shfl_xor_sync(~0u, s, o);
        float inv = 1.f / s;
#pragma unroll
        for (int t = 0; t < 24; t++) sattn[hh * NRES + t * 32 + lane] = vals[t] * inv;
    }
    __syncthreads();

    const float* src = in2d + (size_t)i * NRES * PAIRD;
    // 3) prologue: issue stages 0..2
#pragma unroll
    for (int s = 0; s < 3; s++) {
#pragma unroll
        for (int t = 0; t < 2; t++) {
            int f = tid + t * 256;
            int r = f >> 5, c4 = f & 31;
            cp16(sbuf + s * 2048 + r * 128 + c4 * 4,
                 src + (size_t)(s * 16 + r) * PAIRD + c4 * 4);
        }
        cp_commit();
    }

    // 4) write normalized attn back (overlaps with in-flight cp.async)
    for (int f = tid; f < 2304; f += 256) {
        int h = f / 192, q = f % 192;
        ((float4*)(g_logits + ((size_t)h * NRES + i) * NRES))[q] =
            ((const float4*)(sattn + h * NRES))[q];
    }

    // 5) main pipeline
    int g = tid >> 6, cp = tid & 63;
    ull acc0 = 0, acc1 = 0, acc2 = 0;
    const float* a0p = sattn + (g * 3 + 0) * NRES;
    const float* a1p = sattn + (g * 3 + 1) * NRES;
    const float* a2p = sattn + (g * 3 + 2) * NRES;

    for (int s = 0; s < 48; s++) {
        cp_wait2();
        __syncthreads();
        if (s + 3 < 48) {
            int sn = s + 3;
#pragma unroll
            for (int t = 0; t < 2; t++) {
                int f = tid + t * 256;
                int r = f >> 5, c4 = f & 31;
                cp16(sbuf + (sn & 3) * 2048 + r * 128 + c4 * 4,
                     src + (size_t)(sn * 16 + r) * PAIRD + c4 * 4);
            }
        }
        cp_commit();
        const ull* bb = (const ull*)(sbuf + (s & 3) * 2048) + cp;
        int j0 = s * 16;
#pragma unroll
        for (int q4 = 0; q4 < 4; q4++) {
            float4 A0 = *(const float4*)(a0p + j0 + q4 * 4);
            float4 A1 = *(const float4*)(a1p + j0 + q4 * 4);
            float4 A2 = *(const float4*)(a2p + j0 + q4 * 4);
            const ull* dp = bb + (size_t)q4 * 256;
            ull d0 = dp[0], d1 = dp[64], d2 = dp[128], d3 = dp[192];
            fma2(acc0, pk2(A0.x), d0); fma2(acc1, pk2(A1.x), d0); fma2(acc2, pk2(A2.x), d0);
            fma2(acc0, pk2(A0.y), d1); fma2(acc1, pk2(A1.y), d1); fma2(acc2, pk2(A2.y), d1);
            fma2(acc0, pk2(A0.z), d2); fma2(acc1, pk2(A1.z), d2); fma2(acc2, pk2(A2.z), d2);
            fma2(acc0, pk2(A0.w), d3); fma2(acc1, pk2(A1.w), d3); fma2(acc2, pk2(A2.w), d3);
        }
    }
    float2 r0 = upk(acc0), r1 = upk(acc1), r2 = upk(acc2);
    float* dst = g_final + (size_t)i * FINALD + 576;
    *(float2*)(dst + (g * 3 + 0) * PAIRD + 2 * cp) = r0;
    *(float2*)(dst + (g * 3 + 1) * PAIRD + 2 * cp) = r1;
    *(float2*)(dst + (g * 3 + 2) * PAIRD + 2 * cp) = r2;
}

// ---------------- K4b: per-head GEMM for v / vp + rotate-back epilogue ------
__global__ __launch_bounds__(320) void k4b_vattend(const float* __restrict__ rot,
                                                   const float* __restrict__ trans) {
    __shared__ float2 sattn2[64][65];
    __shared__ ull svp[64 * 20];
    __shared__ float srpg[64][24];
    int i0 = blockIdx.x * 64, h = blockIdx.y;
    int tid = threadIdx.x, il = tid & 63, dg = tid >> 6;
    ull acc[4] = {};
    for (int j0 = 0; j0 < NRES; j0 += 64) {
        for (int f = tid; f < 4096; f += 320) {
            int r = f >> 6, c = f & 63;
            float a = g_logits[((size_t)h * NRES + i0 + r) * NRES + j0 + c];
            sattn2[r][c] = make_float2(a, a);
        }
        for (int f = tid; f < 1280; f += 320)
            svp[f] = __ldg((const ull*)(g_vpack2 + ((size_t)h * NRES + j0) * 40) + f);
        __syncthreads();
#pragma unroll 4
        for (int jj = 0; jj < 64; jj++) {
            ull a2 = *(const ull*)&sattn2[il][jj];
            const ulonglong2* wv = (const ulonglong2*)&svp[jj * 20 + dg * 4];
            ulonglong2 w01 = wv[0], w23 = wv[1];
            fma2(acc[0], a2, w01.x); fma2(acc[1], a2, w01.y);
            fma2(acc[2], a2, w23.x); fma2(acc[3], a2, w23.y);
        }
        __syncthreads();
    }
    int n_i = i0 + il;
    float v[8];
#pragma unroll
    for (int q = 0; q < 4; q++) {
        float2 t = upk(acc[q]);
        v[2 * q] = t.x; v[2 * q + 1] = t.y;
    }
    if (dg < 2) {
        float* dst = g_final + (size_t)n_i * FINALD + h * 16 + dg * 8;
#pragma unroll
        for (int t = 0; t < 8; t++) dst[t] = v[t];
    } else {
        int d0 = (dg - 2) * 8;
#pragma unroll
        for (int t = 0; t < 8; t++) srpg[il][d0 + t] = v[t];
    }
    __syncthreads();
    for (int f = tid; f < 512; f += 320) {
        int ii = f >> 3, p = f & 7;
        int n = i0 + ii;
        float vx = srpg[ii][p * 3 + 0] - trans[n * 3 + 0];
        float vy = srpg[ii][p * 3 + 1] - trans[n * 3 + 1];
        float vz = srpg[ii][p * 3 + 2] - trans[n * 3 + 2];
        float nn = 1e-8f;
#pragma unroll
        for (int ic = 0; ic < 3; ic++) {
            float rl = rot[n * 9 + 0 + ic] * vx + rot[n * 9 + 3 + ic] * vy + rot[n * 9 + 6 + ic] * vz;
            g_final[(size_t)n * FINALD + 192 + ic * 96 + h * 8 + p] = rl;
            nn += rl * rl;
        }
        g_final[(size_t)n * FINALD + 480 + h * 8 + p] = sqrtf(nn);
    }
}

// ---------------- K5: output GEMM 768x384, K=2112, split-K=3 (f32x2) --------
__global__ __launch_bounds__(256) void k5_out(const float* __restrict__ out_w) {
    __shared__ float sA[32][65];
    __shared__ ull sB2[32][32];
    int tid = threadIdx.x, tx = tid & 15, ty = tid >> 4;
    int m0 = blockIdx.y * 64, n0 = blockIdx.x * 64;
    int kb = blockIdx.z * 704;
    ull acc[4][2] = {};
    for (int k0 = kb; k0 < kb + 704; k0 += 32) {
        for (int idx = tid; idx < 64 * 32; idx += 256) {
            int m = idx >> 5, kk = idx & 31;
            sA[kk][m] = g_final[(size_t)(m0 + m) * FINALD + k0 + kk];
        }
        for (int idx = tid; idx < 32 * 32; idx += 256) {
            int kk = idx >> 5, op = idx & 31;
            float2 wv = *(const float2*)(out_w + (size_t)(k0 + kk) * OUTD + n0 + op * 2);
            sB2[kk][op] = pk2two(wv.x, wv.y);
        }
        __syncthreads();
#pragma unroll
        for (int kk = 0; kk < 32; kk++) {
            ulonglong2 b01 = *(const ulonglong2*)&sB2[kk][tx * 2];
#pragma unroll
            for (int r = 0; r < 4; r++) {
                ull a2 = pk2(sA[kk][ty * 4 + r]);
                fma2(acc[r][0], a2, b01.x);
                fma2(acc[r][1], a2, b01.y);
            }
        }
        __syncthreads();
    }
#pragma unroll
    for (int r = 0; r < 4; r++) {
        int m = m0 + ty * 4 + r, o = n0 + tx * 4;
        float2 lo = upk(acc[r][0]), hi = upk(acc[r][1]);
        *(float4*)(g_part[blockIdx.z] + (size_t)m * OUTD + o) =
            make_float4(lo.x, lo.y, hi.x, hi.y);
    }
}

__global__ void k5r_reduce(const float* __restrict__ out_b, float* __restrict__ out) {
    int idx = blockIdx.x * 256 + threadIdx.x;
    if (idx < NRES * OUTD) {
        out[idx] = g_part[0][idx] + g_part[1][idx] + g_part[2][idx] + out_b[idx % OUTD];
    }
}

// ---------------- launch ----------------------------------------------------
extern "C" void kernel_launch(void* const* d_in, const int* in_sizes, int n_in,
                              void* d_out, int out_size) {
    const float* in1d  = (const float*)d_in[0];
    const float* in2d  = (const float*)d_in[1];
    const float* rot   = (const float*)d_in[2];
    const float* trans = (const float*)d_in[3];
    const float* qw    = (const float*)d_in[4];
    const float* qb    = (const float*)d_in[5];
    const float* kvw   = (const float*)d_in[6];
    const float* kvb   = (const float*)d_in[7];
    const float* qpw   = (const float*)d_in[8];
    const float* qpb   = (const float*)d_in[9];
    const float* kvpw  = (const float*)d_in[10];
    const float* kvpb  = (const float*)d_in[11];
    const float* tpw   = (const float*)d_in[12];
    const float* w2d   = (const float*)d_in[13];
    const float* b2d   = (const float*)d_in[14];
    const float* ow    = (const float*)d_in[15];
    const float* ob    = (const float*)d_in[16];
    float* out = (float*)d_out;

    cudaFuncSetAttribute(k4a_aover, cudaFuncAttributeMaxDynamicSharedMemorySize, K4A_SMEM);

    k0_prep<<<1728, 256>>>(qw, qb, kvw, kvb, qpw, qpb, kvpw, kvpb, tpw);
    k1a_gemm<<<dim3(18, 12), 256>>>(in1d);
    k1b_pack<<<768, 256>>>(rot, trans);
    k2_logits<<<4608, 128, K2_SMEM>>>(in2d, w2d, b2d);
    k4a_aover<<<768, 256, K4A_SMEM>>>(in2d);
    k4b_vattend<<<dim3(12, 12), 320>>>(rot, trans);
    k5_out<<<dim3(6, 12, 3), 256>>>(ow);
    k5r_reduce<<<1152, 256>>>(ob, out);
}

// round 8
// speedup vs baseline: 1.8025x; 1.8025x over previous
#include <cuda_runtime.h>
#include <math.h>

#define NRES 768
#define MSAD 384
#define NH 12
#define PAIRD 128
#define OUTD 384
#define PROJ 1152
#define FINALD 2112

typedef unsigned long long ull;

// ---------------- f32x2 helpers (Blackwell packed fp32) ---------------------
__device__ __forceinline__ ull pk2(float v) {
    ull r; asm("mov.b64 %0, {%1, %1};" : "=l"(r) : "f"(v)); return r;
}
__device__ __forceinline__ ull pk2two(float lo, float hi) {
    ull r; asm("mov.b64 %0, {%1, %2};" : "=l"(r) : "f"(lo), "f"(hi)); return r;
}
__device__ __forceinline__ void fma2(ull& d, ull a, ull b) {
    asm("fma.rn.f32x2 %0, %1, %2, %0;" : "+l"(d) : "l"(a), "l"(b));
}
__device__ __forceinline__ float2 upk(ull v) {
    float2 r; asm("mov.b64 {%0, %1}, %2;" : "=f"(r.x), "=f"(r.y) : "l"(v)); return r;
}
// ---------------- cp.async helpers ------------------------------------------
__device__ __forceinline__ void cp16(void* dst, const void* src) {
    unsigned d = (unsigned)__cvta_generic_to_shared(dst);
    asm volatile("cp.async.cg.shared.global [%0], [%1], 16;" :: "r"(d), "l"(src));
}
__device__ __forceinline__ void cp_commit() {
    asm volatile("cp.async.commit_group;" ::: "memory");
}
__device__ __forceinline__ void cp_wait2() {
    asm volatile("cp.async.wait_group 2;" ::: "memory");
}

// ---------------- scratch (device globals; no allocation allowed) ----------
__device__ float g_wcat[MSAD * PROJ];
__device__ float g_bcat[PROJ];
__device__ float g_pw[NH];
__device__ float g_proj[NRES * PROJ];
__device__ float g_qpack[NH * NRES * 28];
__device__ float g_kpack[NH * NRES * 32];
__device__ float g_vpack2[NH * NRES * 40];
__device__ float g_logits[NH * NRES * NRES]; // a2d (k2) -> attn (k3)
__device__ float g_final[NRES * FINALD];
__device__ float g_part[3][NRES * OUTD];

// ---------------- K0 --------------------------------------------------------
__global__ void k0_prep(const float* __restrict__ qw, const float* __restrict__ qb,
                        const float* __restrict__ kvw, const float* __restrict__ kvb,
                        const float* __restrict__ qpw, const float* __restrict__ qpb,
                        const float* __restrict__ kvpw, const float* __restrict__ kvpb,
                        const float* __restrict__ tpw) {
    int idx = blockIdx.x * blockDim.x + threadIdx.x;
    if (idx < MSAD * PROJ) {
        int k = idx / PROJ, o = idx % PROJ;
        float v;
        if (o < 192)      v = qw[k * 192 + o];
        else if (o < 576) v = kvw[k * 384 + (o - 192)];
        else if (o < 720) v = qpw[k * 144 + (o - 576)];
        else              v = kvpw[k * 432 + (o - 720)];
        g_wcat[idx] = v;
    }
    if (idx < PROJ) {
        float b;
        if (idx < 192)      b = qb[idx];
        else if (idx < 576) b = kvb[idx - 192];
        else if (idx < 720) b = qpb[idx - 576];
        else                b = kvpb[idx - 720];
        g_bcat[idx] = b;
    }
    if (idx < NH) {
        float x = tpw[idx];
        float sp = (x > 20.f) ? x : log1pf(__expf(x));
        g_pw[idx] = sp * 0.13608276348795434f; // sqrt(1/54)
    }
}

// ---------------- K1a: projection GEMM 768x1152x384 (f32x2) -----------------
__global__ __launch_bounds__(256) void k1a_gemm(const float* __restrict__ in1d) {
    __shared__ float sA[32][65];
    __shared__ ull sB2[32][32];
    int tid = threadIdx.x;
    int tx = tid & 15, ty = tid >> 4;
    int m0 = blockIdx.y * 64, n0 = blockIdx.x * 64;
    ull acc[4][2] = {};
    for (int k0 = 0; k0 < MSAD; k0 += 32) {
        for (int idx = tid; idx < 64 * 32; idx += 256) {
            int m = idx >> 5, kk = idx & 31;
            sA[kk][m] = in1d[(m0 + m) * MSAD + k0 + kk];
        }
        for (int idx = tid; idx < 32 * 32; idx += 256) {
            int kk = idx >> 5, op = idx & 31;
            float2 w = *(const float2*)(g_wcat + (size_t)(k0 + kk) * PROJ + n0 + op * 2);
            sB2[kk][op] = pk2two(w.x, w.y);
        }
        __syncthreads();
#pragma unroll
        for (int kk = 0; kk < 32; kk++) {
            ulonglong2 b01 = *(const ulonglong2*)&sB2[kk][tx * 2];
#pragma unroll
            for (int r = 0; r < 4; r++) {
                ull a2 = pk2(sA[kk][ty * 4 + r]);
                fma2(acc[r][0], a2, b01.x);
                fma2(acc[r][1], a2, b01.y);
            }
        }
        __syncthreads();
    }
#pragma unroll
    for (int r = 0; r < 4; r++) {
        int m = m0 + ty * 4 + r, o = n0 + tx * 4;
        float2 lo = upk(acc[r][0]), hi = upk(acc[r][1]);
        g_proj[(size_t)m * PROJ + o + 0] = lo.x + g_bcat[o + 0];
        g_proj[(size_t)m * PROJ + o + 1] = lo.y + g_bcat[o + 1];
        g_proj[(size_t)m * PROJ + o + 2] = hi.x + g_bcat[o + 2];
        g_proj[(size_t)m * PROJ + o + 3] = hi.y + g_bcat[o + 3];
    }
}

// ---------------- K1b: apply rotations, pack q/k/v --------------------------
__global__ __launch_bounds__(256) void k1b_pack(const float* __restrict__ rot,
                                                const float* __restrict__ trans) {
    __shared__ float sp[PROJ];
    __shared__ float srot[9], strans[3], spw[12];
    __shared__ float sg[192 * 3];
    int n = blockIdx.x, tid = threadIdx.x;
    for (int t = tid; t < PROJ; t += 256) sp[t] = g_proj[n * PROJ + t];
    if (tid < 9) srot[tid] = rot[n * 9 + tid];
    if (tid < 3) strans[tid] = trans[n * 3 + tid];
    if (tid < 12) spw[tid] = g_pw[tid];
    __syncthreads();

    if (tid < 192) {
        int h = tid >> 4, d = tid & 15;
        g_qpack[(h * NRES + n) * 28 + d] = sp[tid] * 0.14433756729740643f; // 1/sqrt(48)
    }
    for (int t = tid; t < 384; t += 256) {
        int h = t >> 5, d = t & 31;
        if (d < 16) g_kpack[(h * NRES + n) * 32 + d] = sp[192 + t];
        else        g_vpack2[((size_t)h * NRES + n) * 40 + (d - 16)] = sp[192 + t];
    }
    if (tid < 192) {
        float l0, l1, l2;
        if (tid < 48) { l0 = sp[576 + tid]; l1 = sp[576 + 48 + tid]; l2 = sp[576 + 96 + tid]; }
        else { int vs = tid - 48; l0 = sp[720 + vs]; l1 = sp[720 + 144 + vs]; l2 = sp[720 + 288 + vs]; }
#pragma unroll
        for (int c = 0; c < 3; c++)
            sg[tid * 3 + c] = srot[c * 3 + 0] * l0 + srot[c * 3 + 1] * l1 + srot[c * 3 + 2] * l2 + strans[c];
    }
    __syncthreads();
    if (tid < 48) {
        int h = tid >> 2, p = tid & 3;
        float pw = spw[h];
#pragma unroll
        for (int c = 0; c < 3; c++)
            g_qpack[(h * NRES + n) * 28 + 16 + p * 3 + c] = pw * sg[tid * 3 + c];
    } else if (tid < 192) {
        int vs = tid - 48, h = vs / 12, s = vs % 12;
        if (s < 4) {
#pragma unroll
            for (int c = 0; c < 3; c++)
                g_kpack[(h * NRES + n) * 32 + 16 + s * 3 + c] = sg[tid * 3 + c];
        } else {
#pragma unroll
            for (int c = 0; c < 3; c++)
                g_vpack2[((size_t)h * NRES + n) * 40 + 16 + (s - 4) * 3 + c] = sg[tid * 3 + c];
        }
    }
    if (tid >= 192 && tid < 204) {
        int h = tid - 192;
        float s2 = 0.f;
        for (int s = 0; s < 4; s++)
            for (int c = 0; c < 3; c++) {
                float v = sg[(48 + h * 12 + s) * 3 + c];
                s2 += v * v;
            }
        g_kpack[(h * NRES + n) * 32 + 28] = -0.5f * spw[h] * s2;
    }
}

// ---------------- K2: a2d = (in2d @ W2d + b) * scale -> g_logits ------------
// (R3 design, benchmarked 97us: single-buffer smem stage, thread = row)
__global__ __launch_bounds__(256) void k2_a2d(const float* __restrict__ in2d,
                                              const float* __restrict__ w2d,
                                              const float* __restrict__ b2d) {
    __shared__ float sA[256][33];
    __shared__ ull sw2[128][6];
    __shared__ float sb[12];
    int tid = threadIdx.x;
    for (int f = tid; f < 128 * 6; f += 256) {
        int c = f / 6, hp = f % 6;
        float2 w = *(const float2*)(w2d + c * 12 + hp * 2);
        sw2[c][hp] = pk2two(w.x, w.y);
    }
    if (tid < 12) sb[tid] = b2d[tid];
    size_t p0 = (size_t)blockIdx.x * 256;
    ull acc[6] = {};
    for (int k0 = 0; k0 < 128; k0 += 32) {
        __syncthreads();
        for (int f = tid; f < 2048; f += 256) {
            int r = f >> 3, c4 = f & 7;
            float4 v = __ldg((const float4*)(in2d + (p0 + r) * 128 + k0) + c4);
            sA[r][c4 * 4 + 0] = v.x; sA[r][c4 * 4 + 1] = v.y;
            sA[r][c4 * 4 + 2] = v.z; sA[r][c4 * 4 + 3] = v.w;
        }
        __syncthreads();
#pragma unroll
        for (int k = 0; k < 32; k++) {
            float a = sA[tid][k];
            ull a2 = pk2(a);
            ulonglong2 w01 = *(const ulonglong2*)&sw2[k0 + k][0];
            ulonglong2 w23 = *(const ulonglong2*)&sw2[k0 + k][2];
            ulonglong2 w45 = *(const ulonglong2*)&sw2[k0 + k][4];
            fma2(acc[0], a2, w01.x); fma2(acc[1], a2, w01.y);
            fma2(acc[2], a2, w23.x); fma2(acc[3], a2, w23.y);
            fma2(acc[4], a2, w45.x); fma2(acc[5], a2, w45.y);
        }
    }
    size_t p = p0 + tid;
    int i = (int)(p / NRES), j = (int)(p % NRES);
    float res[12];
#pragma unroll
    for (int hp = 0; hp < 6; hp++) {
        float2 v = upk(acc[hp]);
        res[2 * hp] = v.x; res[2 * hp + 1] = v.y;
    }
#pragma unroll
    for (int h = 0; h < 12; h++)
        g_logits[((size_t)h * NRES + i) * NRES + j] = (res[h] + sb[h]) * 0.5773502691896258f;
}

// ---------------- K3: qk scalar+point logits + softmax ----------------------
// Phase1: f32x2 qk dot (thread = j); Phase2: warp-per-row softmax (8 warps = 8 rows)
__global__ __launch_bounds__(256) void k3_softmax() {
    __shared__ float srow[8][NRES];
    __shared__ ull su2[8][14];
    int h = blockIdx.y, i0 = blockIdx.x * 8;
    int tid = threadIdx.x;
    for (int t = tid; t < 8 * 14; t += 256) {
        int i8 = t / 14, dp = t % 14;
        const float* qp = g_qpack + ((size_t)h * NRES + (i0 + i8)) * 28 + dp * 2;
        su2[i8][dp] = pk2two(qp[0], qp[1]);
    }
    __syncthreads();
    for (int jj = 0; jj < 3; jj++) {
        int j = jj * 256 + tid;
        const float4* kp4 = (const float4*)(g_kpack + (size_t)(h * NRES + j) * 32);
        ull wr2[14];
        float bias;
        {
            float4 v0 = kp4[0], v1 = kp4[1], v2 = kp4[2], v3 = kp4[3];
            float4 v4 = kp4[4], v5 = kp4[5], v6 = kp4[6], v7 = kp4[7];
            wr2[0]  = pk2two(v0.x, v0.y); wr2[1]  = pk2two(v0.z, v0.w);
            wr2[2]  = pk2two(v1.x, v1.y); wr2[3]  = pk2two(v1.z, v1.w);
            wr2[4]  = pk2two(v2.x, v2.y); wr2[5]  = pk2two(v2.z, v2.w);
            wr2[6]  = pk2two(v3.x, v3.y); wr2[7]  = pk2two(v3.z, v3.w);
            wr2[8]  = pk2two(v4.x, v4.y); wr2[9]  = pk2two(v4.z, v4.w);
            wr2[10] = pk2two(v5.x, v5.y); wr2[11] = pk2two(v5.z, v5.w);
            wr2[12] = pk2two(v6.x, v6.y); wr2[13] = pk2two(v6.z, v6.w);
            bias = v7.x;
        }
#pragma unroll
        for (int i8 = 0; i8 < 8; i8++) {
            ull acc2 = 0;
#pragma unroll
            for (int dp = 0; dp < 14; dp++) fma2(acc2, su2[i8][dp], wr2[dp]);
            float2 t = upk(acc2);
            srow[i8][j] = t.x + t.y + bias
                        + g_logits[((size_t)h * NRES + (i0 + i8)) * NRES + j];
        }
    }
    __syncthreads();
    // warp w owns row w
    int w = tid >> 5, lane = tid & 31;
    float vals[24];
    float m = -1e30f;
#pragma unroll
    for (int t = 0; t < 24; t++) {
        vals[t] = srow[w][t * 32 + lane];
        m = fmaxf(m, vals[t]);
    }
#pragma unroll
    for (int o = 16; o > 0; o >>= 1) m = fmaxf(m, __shfl_xor_sync(~0u, m, o));
    float s = 0.f;
#pragma unroll
    for (int t = 0; t < 24; t++) {
        float e = __expf(vals[t] - m);
        vals[t] = e; s += e;
    }
#pragma unroll
    for (int o = 16; o > 0; o >>= 1) s += __shfl_xor_sync(~0u, s, o);
    float inv = 1.f / s;
    float* dst = g_logits + ((size_t)h * NRES + (i0 + w)) * NRES;
#pragma unroll
    for (int t = 0; t < 24; t++) dst[t * 32 + lane] = vals[t] * inv;
}

// ---------------- K4a: a_over_2d (cp.async 4-deep pipeline) -----------------
// One block per query row i, 256 threads.
// smem: sattn float[12*768] @0 (36864), sbuf float[4][16*128] @36864 (32768)
#define K4A_SMEM 69632
__global__ __launch_bounds__(256) void k4a_aover(const float* __restrict__ in2d) {
    extern __shared__ char smraw[];
    float* sattn = (float*)smraw;
    float* sbuf  = (float*)(smraw + 36864);
    int i = blockIdx.x, tid = threadIdx.x;

    const float* src = in2d + (size_t)i * NRES * PAIRD;
    // prologue: issue stages 0..2
#pragma unroll
    for (int s = 0; s < 3; s++) {
#pragma unroll
        for (int t = 0; t < 2; t++) {
            int f = tid + t * 256;
            int r = f >> 5, c4 = f & 31;
            cp16(sbuf + s * 2048 + r * 128 + c4 * 4,
                 src + (size_t)(s * 16 + r) * PAIRD + c4 * 4);
        }
        cp_commit();
    }
    // load normalized attention row (overlaps with in-flight cp.async)
    for (int f = tid; f < 2304; f += 256) {
        int h = f / 192, q = f % 192;
        ((float4*)(sattn + h * NRES))[q] =
            __ldg((const float4*)(g_logits + ((size_t)h * NRES + i) * NRES) + q);
    }
    __syncthreads();

    int g = tid >> 6, cp = tid & 63;
    ull acc0 = 0, acc1 = 0, acc2 = 0;
    const float* a0p = sattn + (g * 3 + 0) * NRES;
    const float* a1p = sattn + (g * 3 + 1) * NRES;
    const float* a2p = sattn + (g * 3 + 2) * NRES;

    for (int s = 0; s < 48; s++) {
        cp_wait2();
        __syncthreads();
        if (s + 3 < 48) {
            int sn = s + 3;
#pragma unroll
            for (int t = 0; t < 2; t++) {
                int f = tid + t * 256;
                int r = f >> 5, c4 = f & 31;
                cp16(sbuf + (sn & 3) * 2048 + r * 128 + c4 * 4,
                     src + (size_t)(sn * 16 + r) * PAIRD + c4 * 4);
            }
        }
        cp_commit();
        const ull* bb = (const ull*)(sbuf + (s & 3) * 2048) + cp;
        int j0 = s * 16;
#pragma unroll
        for (int q4 = 0; q4 < 4; q4++) {
            float4 A0 = *(const float4*)(a0p + j0 + q4 * 4);
            float4 A1 = *(const float4*)(a1p + j0 + q4 * 4);
            float4 A2 = *(const float4*)(a2p + j0 + q4 * 4);
            const ull* dp = bb + (size_t)q4 * 256;
            ull d0 = dp[0], d1 = dp[64], d2 = dp[128], d3 = dp[192];
            fma2(acc0, pk2(A0.x), d0); fma2(acc1, pk2(A1.x), d0); fma2(acc2, pk2(A2.x), d0);
            fma2(acc0, pk2(A0.y), d1); fma2(acc1, pk2(A1.y), d1); fma2(acc2, pk2(A2.y), d1);
            fma2(acc0, pk2(A0.z), d2); fma2(acc1, pk2(A1.z), d2); fma2(acc2, pk2(A2.z), d2);
            fma2(acc0, pk2(A0.w), d3); fma2(acc1, pk2(A1.w), d3); fma2(acc2, pk2(A2.w), d3);
        }
    }
    float2 r0 = upk(acc0), r1 = upk(acc1), r2 = upk(acc2);
    float* dst = g_final + (size_t)i * FINALD + 576;
    *(float2*)(dst + (g * 3 + 0) * PAIRD + 2 * cp) = r0;
    *(float2*)(dst + (g * 3 + 1) * PAIRD + 2 * cp) = r1;
    *(float2*)(dst + (g * 3 + 2) * PAIRD + 2 * cp) = r2;
}

// ---------------- K4b: per-head GEMM for v / vp + rotate-back epilogue ------
__global__ __launch_bounds__(320) void k4b_vattend(const float* __restrict__ rot,
                                                   const float* __restrict__ trans) {
    __shared__ float2 sattn2[64][65];
    __shared__ ull svp[64 * 20];
    __shared__ float srpg[64][24];
    int i0 = blockIdx.x * 64, h = blockIdx.y;
    int tid = threadIdx.x, il = tid & 63, dg = tid >> 6;
    ull acc[4] = {};
    for (int j0 = 0; j0 < NRES; j0 += 64) {
        for (int f = tid; f < 4096; f += 320) {
            int r = f >> 6, c = f & 63;
            float a = g_logits[((size_t)h * NRES + i0 + r) * NRES + j0 + c];
            sattn2[r][c] = make_float2(a, a);
        }
        for (int f = tid; f < 1280; f += 320)
            svp[f] = __ldg((const ull*)(g_vpack2 + ((size_t)h * NRES + j0) * 40) + f);
        __syncthreads();
#pragma unroll 4
        for (int jj = 0; jj < 64; jj++) {
            ull a2 = *(const ull*)&sattn2[il][jj];
            const ulonglong2* wv = (const ulonglong2*)&svp[jj * 20 + dg * 4];
            ulonglong2 w01 = wv[0], w23 = wv[1];
            fma2(acc[0], a2, w01.x); fma2(acc[1], a2, w01.y);
            fma2(acc[2], a2, w23.x); fma2(acc[3], a2, w23.y);
        }
        __syncthreads();
    }
    int n_i = i0 + il;
    float v[8];
#pragma unroll
    for (int q = 0; q < 4; q++) {
        float2 t = upk(acc[q]);
        v[2 * q] = t.x; v[2 * q + 1] = t.y;
    }
    if (dg < 2) {
        float* dst = g_final + (size_t)n_i * FINALD + h * 16 + dg * 8;
#pragma unroll
        for (int t = 0; t < 8; t++) dst[t] = v[t];
    } else {
        int d0 = (dg - 2) * 8;
#pragma unroll
        for (int t = 0; t < 8; t++) srpg[il][d0 + t] = v[t];
    }
    __syncthreads();
    for (int f = tid; f < 512; f += 320) {
        int ii = f >> 3, p = f & 7;
        int n = i0 + ii;
        float vx = srpg[ii][p * 3 + 0] - trans[n * 3 + 0];
        float vy = srpg[ii][p * 3 + 1] - trans[n * 3 + 1];
        float vz = srpg[ii][p * 3 + 2] - trans[n * 3 + 2];
        float nn = 1e-8f;
#pragma unroll
        for (int ic = 0; ic < 3; ic++) {
            float rl = rot[n * 9 + 0 + ic] * vx + rot[n * 9 + 3 + ic] * vy + rot[n * 9 + 6 + ic] * vz;
            g_final[(size_t)n * FINALD + 192 + ic * 96 + h * 8 + p] = rl;
            nn += rl * rl;
        }
        g_final[(size_t)n * FINALD + 480 + h * 8 + p] = sqrtf(nn);
    }
}

// ---------------- K5: output GEMM 768x384, K=2112, split-K=3 (f32x2) --------
__global__ __launch_bounds__(256) void k5_out(const float* __restrict__ out_w) {
    __shared__ float sA[32][65];
    __shared__ ull sB2[32][32];
    int tid = threadIdx.x, tx = tid & 15, ty = tid >> 4;
    int m0 = blockIdx.y * 64, n0 = blockIdx.x * 64;
    int kb = blockIdx.z * 704;
    ull acc[4][2] = {};
    for (int k0 = kb; k0 < kb + 704; k0 += 32) {
        for (int idx = tid; idx < 64 * 32; idx += 256) {
            int m = idx >> 5, kk = idx & 31;
            sA[kk][m] = g_final[(size_t)(m0 + m) * FINALD + k0 + kk];
        }
        for (int idx = tid; idx < 32 * 32; idx += 256) {
            int kk = idx >> 5, op = idx & 31;
            float2 wv = *(const float2*)(out_w + (size_t)(k0 + kk) * OUTD + n0 + op * 2);
            sB2[kk][op] = pk2two(wv.x, wv.y);
        }
        __syncthreads();
#pragma unroll
        for (int kk = 0; kk < 32; kk++) {
            ulonglong2 b01 = *(const ulonglong2*)&sB2[kk][tx * 2];
#pragma unroll
            for (int r = 0; r < 4; r++) {
                ull a2 = pk2(sA[kk][ty * 4 + r]);
                fma2(acc[r][0], a2, b01.x);
                fma2(acc[r][1], a2, b01.y);
            }
        }
        __syncthreads();
    }
#pragma unroll
    for (int r = 0; r < 4; r++) {
        int m = m0 + ty * 4 + r, o = n0 + tx * 4;
        float2 lo = upk(acc[r][0]), hi = upk(acc[r][1]);
        *(float4*)(g_part[blockIdx.z] + (size_t)m * OUTD + o) =
            make_float4(lo.x, lo.y, hi.x, hi.y);
    }
}

__global__ void k5r_reduce(const float* __restrict__ out_b, float* __restrict__ out) {
    int idx = blockIdx.x * 256 + threadIdx.x;
    if (idx < NRES * OUTD) {
        out[idx] = g_part[0][idx] + g_part[1][idx] + g_part[2][idx] + out_b[idx % OUTD];
    }
}

// ---------------- launch ----------------------------------------------------
extern "C" void kernel_launch(void* const* d_in, const int* in_sizes, int n_in,
                              void* d_out, int out_size) {
    const float* in1d  = (const float*)d_in[0];
    const float* in2d  = (const float*)d_in[1];
    const float* rot   = (const float*)d_in[2];
    const float* trans = (const float*)d_in[3];
    const float* qw    = (const float*)d_in[4];
    const float* qb    = (const float*)d_in[5];
    const float* kvw   = (const float*)d_in[6];
    const float* kvb   = (const float*)d_in[7];
    const float* qpw   = (const float*)d_in[8];
    const float* qpb   = (const float*)d_in[9];
    const float* kvpw  = (const float*)d_in[10];
    const float* kvpb  = (const float*)d_in[11];
    const float* tpw   = (const float*)d_in[12];
    const float* w2d   = (const float*)d_in[13];
    const float* b2d   = (const float*)d_in[14];
    const float* ow    = (const float*)d_in[15];
    const float* ob    = (const float*)d_in[16];
    float* out = (float*)d_out;

    cudaFuncSetAttribute(k4a_aover, cudaFuncAttributeMaxDynamicSharedMemorySize, K4A_SMEM);

    k0_prep<<<1728, 256>>>(qw, qb, kvw, kvb, qpw, qpb, kvpw, kvpb, tpw);
    k1a_gemm<<<dim3(18, 12), 256>>>(in1d);
    k1b_pack<<<768, 256>>>(rot, trans);
    k2_a2d<<<2304, 256>>>(in2d, w2d, b2d);
    k3_softmax<<<dim3(96, 12), 256>>>();
    k4a_aover<<<768, 256, K4A_SMEM>>>(in2d);
    k4b_vattend<<<dim3(12, 12), 320>>>(rot, trans);
    k5_out<<<dim3(6, 12, 3), 256>>>(ow);
    k5r_reduce<<<1152, 256>>>(ob, out);
}

// round 9
// speedup vs baseline: 2.0338x; 1.1283x over previous
#include <cuda_runtime.h>
#include <math.h>

#define NRES 768
#define MSAD 384
#define NH 12
#define PAIRD 128
#define OUTD 384
#define PROJ 1152
#define FINALD 2112

typedef unsigned long long ull;

// ---------------- f32x2 helpers (Blackwell packed fp32) ---------------------
__device__ __forceinline__ ull pk2(float v) {
    ull r; asm("mov.b64 %0, {%1, %1};" : "=l"(r) : "f"(v)); return r;
}
__device__ __forceinline__ ull pk2two(float lo, float hi) {
    ull r; asm("mov.b64 %0, {%1, %2};" : "=l"(r) : "f"(lo), "f"(hi)); return r;
}
__device__ __forceinline__ void fma2(ull& d, ull a, ull b) {
    asm("fma.rn.f32x2 %0, %1, %2, %0;" : "+l"(d) : "l"(a), "l"(b));
}
__device__ __forceinline__ float2 upk(ull v) {
    float2 r; asm("mov.b64 {%0, %1}, %2;" : "=f"(r.x), "=f"(r.y) : "l"(v)); return r;
}
// ---------------- cp.async helpers ------------------------------------------
__device__ __forceinline__ void cp16(void* dst, const void* src) {
    unsigned d = (unsigned)__cvta_generic_to_shared(dst);
    asm volatile("cp.async.cg.shared.global [%0], [%1], 16;" :: "r"(d), "l"(src));
}
__device__ __forceinline__ void cp_commit() {
    asm volatile("cp.async.commit_group;" ::: "memory");
}
__device__ __forceinline__ void cp_wait2() {
    asm volatile("cp.async.wait_group 2;" ::: "memory");
}

// ---------------- scratch (device globals; no allocation allowed) ----------
__device__ float g_wcat[MSAD * PROJ];
__device__ float g_bcat[PROJ];
__device__ float g_pw[NH];
__device__ float g_proj[NRES * PROJ];
__device__ float g_qpack[NH * NRES * 28];
__device__ float g_kpackT[NH * 32 * NRES];  // [h][d][j], d-major (d28 = bias)
__device__ float g_vpack2[NH * NRES * 40];
__device__ float g_logits[NH * NRES * NRES]; // a2d (k2) -> attn (k3)
__device__ float g_final[NRES * FINALD];
__device__ float g_part[3][NRES * OUTD];

// ---------------- K0 --------------------------------------------------------
__global__ void k0_prep(const float* __restrict__ qw, const float* __restrict__ qb,
                        const float* __restrict__ kvw, const float* __restrict__ kvb,
                        const float* __restrict__ qpw, const float* __restrict__ qpb,
                        const float* __restrict__ kvpw, const float* __restrict__ kvpb,
                        const float* __restrict__ tpw) {
    int idx = blockIdx.x * blockDim.x + threadIdx.x;
    if (idx < MSAD * PROJ) {
        int k = idx / PROJ, o = idx % PROJ;
        float v;
        if (o < 192)      v = qw[k * 192 + o];
        else if (o < 576) v = kvw[k * 384 + (o - 192)];
        else if (o < 720) v = qpw[k * 144 + (o - 576)];
        else              v = kvpw[k * 432 + (o - 720)];
        g_wcat[idx] = v;
    }
    if (idx < PROJ) {
        float b;
        if (idx < 192)      b = qb[idx];
        else if (idx < 576) b = kvb[idx - 192];
        else if (idx < 720) b = qpb[idx - 576];
        else                b = kvpb[idx - 720];
        g_bcat[idx] = b;
    }
    if (idx < NH) {
        float x = tpw[idx];
        float sp = (x > 20.f) ? x : log1pf(__expf(x));
        g_pw[idx] = sp * 0.13608276348795434f; // sqrt(1/54)
    }
}

// ---------------- K1a: projection GEMM 768x1152x384 (f32x2) -----------------
__global__ __launch_bounds__(256) void k1a_gemm(const float* __restrict__ in1d) {
    __shared__ float sA[32][65];
    __shared__ ull sB2[32][32];
    int tid = threadIdx.x;
    int tx = tid & 15, ty = tid >> 4;
    int m0 = blockIdx.y * 64, n0 = blockIdx.x * 64;
    ull acc[4][2] = {};
    for (int k0 = 0; k0 < MSAD; k0 += 32) {
        for (int idx = tid; idx < 64 * 32; idx += 256) {
            int m = idx >> 5, kk = idx & 31;
            sA[kk][m] = in1d[(m0 + m) * MSAD + k0 + kk];
        }
        for (int idx = tid; idx < 32 * 32; idx += 256) {
            int kk = idx >> 5, op = idx & 31;
            float2 w = *(const float2*)(g_wcat + (size_t)(k0 + kk) * PROJ + n0 + op * 2);
            sB2[kk][op] = pk2two(w.x, w.y);
        }
        __syncthreads();
#pragma unroll
        for (int kk = 0; kk < 32; kk++) {
            ulonglong2 b01 = *(const ulonglong2*)&sB2[kk][tx * 2];
#pragma unroll
            for (int r = 0; r < 4; r++) {
                ull a2 = pk2(sA[kk][ty * 4 + r]);
                fma2(acc[r][0], a2, b01.x);
                fma2(acc[r][1], a2, b01.y);
            }
        }
        __syncthreads();
    }
#pragma unroll
    for (int r = 0; r < 4; r++) {
        int m = m0 + ty * 4 + r, o = n0 + tx * 4;
        float2 lo = upk(acc[r][0]), hi = upk(acc[r][1]);
        g_proj[(size_t)m * PROJ + o + 0] = lo.x + g_bcat[o + 0];
        g_proj[(size_t)m * PROJ + o + 1] = lo.y + g_bcat[o + 1];
        g_proj[(size_t)m * PROJ + o + 2] = hi.x + g_bcat[o + 2];
        g_proj[(size_t)m * PROJ + o + 3] = hi.y + g_bcat[o + 3];
    }
}

// ---------------- K1b: apply rotations, pack q/k/v --------------------------
__global__ __launch_bounds__(256) void k1b_pack(const float* __restrict__ rot,
                                                const float* __restrict__ trans) {
    __shared__ float sp[PROJ];
    __shared__ float srot[9], strans[3], spw[12];
    __shared__ float sg[192 * 3];
    int n = blockIdx.x, tid = threadIdx.x;
    for (int t = tid; t < PROJ; t += 256) sp[t] = g_proj[n * PROJ + t];
    if (tid < 9) srot[tid] = rot[n * 9 + tid];
    if (tid < 3) strans[tid] = trans[n * 3 + tid];
    if (tid < 12) spw[tid] = g_pw[tid];
    __syncthreads();

    if (tid < 192) {
        int h = tid >> 4, d = tid & 15;
        g_qpack[(h * NRES + n) * 28 + d] = sp[tid] * 0.14433756729740643f; // 1/sqrt(48)
    }
    for (int t = tid; t < 384; t += 256) {
        int h = t >> 5, d = t & 31;
        if (d < 16) g_kpackT[((size_t)h * 32 + d) * NRES + n] = sp[192 + t];
        else        g_vpack2[((size_t)h * NRES + n) * 40 + (d - 16)] = sp[192 + t];
    }
    if (tid < 192) {
        float l0, l1, l2;
        if (tid < 48) { l0 = sp[576 + tid]; l1 = sp[576 + 48 + tid]; l2 = sp[576 + 96 + tid]; }
        else { int vs = tid - 48; l0 = sp[720 + vs]; l1 = sp[720 + 144 + vs]; l2 = sp[720 + 288 + vs]; }
#pragma unroll
        for (int c = 0; c < 3; c++)
            sg[tid * 3 + c] = srot[c * 3 + 0] * l0 + srot[c * 3 + 1] * l1 + srot[c * 3 + 2] * l2 + strans[c];
    }
    __syncthreads();
    if (tid < 48) {
        int h = tid >> 2, p = tid & 3;
        float pw = spw[h];
#pragma unroll
        for (int c = 0; c < 3; c++)
            g_qpack[(h * NRES + n) * 28 + 16 + p * 3 + c] = pw * sg[tid * 3 + c];
    } else if (tid < 192) {
        int vs = tid - 48, h = vs / 12, s = vs % 12;
        if (s < 4) {
#pragma unroll
            for (int c = 0; c < 3; c++)
                g_kpackT[((size_t)h * 32 + 16 + s * 3 + c) * NRES + n] = sg[tid * 3 + c];
        } else {
#pragma unroll
            for (int c = 0; c < 3; c++)
                g_vpack2[((size_t)h * NRES + n) * 40 + 16 + (s - 4) * 3 + c] = sg[tid * 3 + c];
        }
    }
    if (tid >= 192 && tid < 204) {
        int h = tid - 192;
        float s2 = 0.f;
        for (int s = 0; s < 4; s++)
            for (int c = 0; c < 3; c++) {
                float v = sg[(48 + h * 12 + s) * 3 + c];
                s2 += v * v;
            }
        g_kpackT[((size_t)h * 32 + 28) * NRES + n] = -0.5f * spw[h] * s2;
    }
}

// ---------------- K2: a2d GEMM, register-staged ping-pong -------------------
// 16-col chunks; next chunk's LDGs issued into regs, overlapping compute.
__global__ __launch_bounds__(256) void k2_a2d(const float* __restrict__ in2d,
                                              const float* __restrict__ w2d,
                                              const float* __restrict__ b2d) {
    __shared__ float sA[256 * 17];
    __shared__ ull sw2[128 * 6];
    __shared__ float sb[12];
    int tid = threadIdx.x;
    for (int f = tid; f < 128 * 6; f += 256) {
        int c = f / 6, hp = f % 6;
        float2 w = *(const float2*)(w2d + c * 12 + hp * 2);
        sw2[f] = pk2two(w.x, w.y);
    }
    if (tid < 12) sb[tid] = b2d[tid];
    size_t p0 = (size_t)blockIdx.x * 256;
    const float* src = in2d + p0 * PAIRD;

    // preload chunk 0 into staging regs (4 float4/thread)
    float4 st[4];
#pragma unroll
    for (int t = 0; t < 4; t++) {
        int f = tid + t * 256;            // 0..1023
        int r = f >> 2, c4 = f & 3;
        st[t] = __ldg((const float4*)(src + (size_t)r * PAIRD) + c4);
    }
    ull acc[6] = {};
#pragma unroll
    for (int ck = 0; ck < 8; ck++) {
        // store staged regs (scalar stores; pitch 17 keeps LDS conflict-free)
#pragma unroll
        for (int t = 0; t < 4; t++) {
            int f = tid + t * 256;
            int r = f >> 2, c4 = f & 3;
            float* d = &sA[r * 17 + c4 * 4];
            d[0] = st[t].x; d[1] = st[t].y; d[2] = st[t].z; d[3] = st[t].w;
        }
        __syncthreads();
        // issue next chunk's loads (overlap with compute below)
        if (ck + 1 < 8) {
#pragma unroll
            for (int t = 0; t < 4; t++) {
                int f = tid + t * 256;
                int r = f >> 2, c4 = f & 3;
                st[t] = __ldg((const float4*)(src + (size_t)r * PAIRD + (ck + 1) * 16) + c4);
            }
        }
        const float* A = &sA[tid * 17];
#pragma unroll
        for (int k = 0; k < 16; k++) {
            ull a2 = pk2(A[k]);
            const ull* w = &sw2[(ck * 16 + k) * 6];
            ulonglong2 w01 = *(const ulonglong2*)(w + 0);
            ulonglong2 w23 = *(const ulonglong2*)(w + 2);
            ulonglong2 w45 = *(const ulonglong2*)(w + 4);
            fma2(acc[0], a2, w01.x); fma2(acc[1], a2, w01.y);
            fma2(acc[2], a2, w23.x); fma2(acc[3], a2, w23.y);
            fma2(acc[4], a2, w45.x); fma2(acc[5], a2, w45.y);
        }
        __syncthreads();
    }
    size_t p = p0 + tid;
    int i = (int)(p / NRES), j = (int)(p % NRES);
    float res[12];
#pragma unroll
    for (int hp = 0; hp < 6; hp++) {
        float2 v = upk(acc[hp]);
        res[2 * hp] = v.x; res[2 * hp + 1] = v.y;
    }
#pragma unroll
    for (int h = 0; h < 12; h++)
        g_logits[((size_t)h * NRES + i) * NRES + j] = (res[h] + sb[h]) * 0.5773502691896258f;
}

// ---------------- K3: qk logits (coalesced kpackT) + softmax ----------------
__global__ __launch_bounds__(256) void k3_softmax() {
    __shared__ float srow[8][NRES];
    __shared__ ull su2[8][14];
    int h = blockIdx.y, i0 = blockIdx.x * 8;
    int tid = threadIdx.x;
    for (int t = tid; t < 8 * 14; t += 256) {
        int i8 = t / 14, dp = t % 14;
        const float* qp = g_qpack + ((size_t)h * NRES + (i0 + i8)) * 28 + dp * 2;
        su2[i8][dp] = pk2two(qp[0], qp[1]);
    }
    __syncthreads();
    const float* kbase = g_kpackT + (size_t)h * 32 * NRES;
    for (int jj = 0; jj < 3; jj++) {
        int j = jj * 256 + tid;
        const float* kb = kbase + j;
        ull wr2[14];
#pragma unroll
        for (int dp = 0; dp < 14; dp++)
            wr2[dp] = pk2two(__ldg(kb + (size_t)(2 * dp) * NRES),
                             __ldg(kb + (size_t)(2 * dp + 1) * NRES));
        float bias = __ldg(kb + (size_t)28 * NRES);
#pragma unroll
        for (int i8 = 0; i8 < 8; i8++) {
            ull acc2 = 0;
#pragma unroll
            for (int dp = 0; dp < 14; dp++) fma2(acc2, su2[i8][dp], wr2[dp]);
            float2 t = upk(acc2);
            srow[i8][j] = t.x + t.y + bias
                        + g_logits[((size_t)h * NRES + (i0 + i8)) * NRES + j];
        }
    }
    __syncthreads();
    // warp w owns row w
    int w = tid >> 5, lane = tid & 31;
    float vals[24];
    float m = -1e30f;
#pragma unroll
    for (int t = 0; t < 24; t++) {
        vals[t] = srow[w][t * 32 + lane];
        m = fmaxf(m, vals[t]);
    }
#pragma unroll
    for (int o = 16; o > 0; o >>= 1) m = fmaxf(m, __shfl_xor_sync(~0u, m, o));
    float s = 0.f;
#pragma unroll
    for (int t = 0; t < 24; t++) {
        float e = __expf(vals[t] - m);
        vals[t] = e; s += e;
    }
#pragma unroll
    for (int o = 16; o > 0; o >>= 1) s += __shfl_xor_sync(~0u, s, o);
    float inv = 1.f / s;
    float* dst = g_logits + ((size_t)h * NRES + (i0 + w)) * NRES;
#pragma unroll
    for (int t = 0; t < 24; t++) dst[t * 32 + lane] = vals[t] * inv;
}

// ---------------- K4a: a_over_2d (cp.async 4-deep pipeline) -----------------
#define K4A_SMEM 69632
__global__ __launch_bounds__(256) void k4a_aover(const float* __restrict__ in2d) {
    extern __shared__ char smraw[];
    float* sattn = (float*)smraw;
    float* sbuf  = (float*)(smraw + 36864);
    int i = blockIdx.x, tid = threadIdx.x;

    const float* src = in2d + (size_t)i * NRES * PAIRD;
#pragma unroll
    for (int s = 0; s < 3; s++) {
#pragma unroll
        for (int t = 0; t < 2; t++) {
            int f = tid + t * 256;
            int r = f >> 5, c4 = f & 31;
            cp16(sbuf + s * 2048 + r * 128 + c4 * 4,
                 src + (size_t)(s * 16 + r) * PAIRD + c4 * 4);
        }
        cp_commit();
    }
    for (int f = tid; f < 2304; f += 256) {
        int h = f / 192, q = f % 192;
        ((float4*)(sattn + h * NRES))[q] =
            __ldg((const float4*)(g_logits + ((size_t)h * NRES + i) * NRES) + q);
    }
    __syncthreads();

    int g = tid >> 6, cp = tid & 63;
    ull acc0 = 0, acc1 = 0, acc2 = 0;
    const float* a0p = sattn + (g * 3 + 0) * NRES;
    const float* a1p = sattn + (g * 3 + 1) * NRES;
    const float* a2p = sattn + (g * 3 + 2) * NRES;

    for (int s = 0; s < 48; s++) {
        cp_wait2();
        __syncthreads();
        if (s + 3 < 48) {
            int sn = s + 3;
#pragma unroll
            for (int t = 0; t < 2; t++) {
                int f = tid + t * 256;
                int r = f >> 5, c4 = f & 31;
                cp16(sbuf + (sn & 3) * 2048 + r * 128 + c4 * 4,
                     src + (size_t)(sn * 16 + r) * PAIRD + c4 * 4);
            }
        }
        cp_commit();
        const ull* bb = (const ull*)(sbuf + (s & 3) * 2048) + cp;
        int j0 = s * 16;
#pragma unroll
        for (int q4 = 0; q4 < 4; q4++) {
            float4 A0 = *(const float4*)(a0p + j0 + q4 * 4);
            float4 A1 = *(const float4*)(a1p + j0 + q4 * 4);
            float4 A2 = *(const float4*)(a2p + j0 + q4 * 4);
            const ull* dp = bb + (size_t)q4 * 256;
            ull d0 = dp[0], d1 = dp[64], d2 = dp[128], d3 = dp[192];
            fma2(acc0, pk2(A0.x), d0); fma2(acc1, pk2(A1.x), d0); fma2(acc2, pk2(A2.x), d0);
            fma2(acc0, pk2(A0.y), d1); fma2(acc1, pk2(A1.y), d1); fma2(acc2, pk2(A2.y), d1);
            fma2(acc0, pk2(A0.z), d2); fma2(acc1, pk2(A1.z), d2); fma2(acc2, pk2(A2.z), d2);
            fma2(acc0, pk2(A0.w), d3); fma2(acc1, pk2(A1.w), d3); fma2(acc2, pk2(A2.w), d3);
        }
    }
    float2 r0 = upk(acc0), r1 = upk(acc1), r2 = upk(acc2);
    float* dst = g_final + (size_t)i * FINALD + 576;
    *(float2*)(dst + (g * 3 + 0) * PAIRD + 2 * cp) = r0;
    *(float2*)(dst + (g * 3 + 1) * PAIRD + 2 * cp) = r1;
    *(float2*)(dst + (g * 3 + 2) * PAIRD + 2 * cp) = r2;
}

// ---------------- K4b: per-head GEMM for v / vp + rotate-back epilogue ------
__global__ __launch_bounds__(320) void k4b_vattend(const float* __restrict__ rot,
                                                   const float* __restrict__ trans) {
    __shared__ float2 sattn2[64][65];
    __shared__ ull svp[64 * 20];
    __shared__ float srpg[64][24];
    int i0 = blockIdx.x * 64, h = blockIdx.y;
    int tid = threadIdx.x, il = tid & 63, dg = tid >> 6;
    ull acc[4] = {};
    for (int j0 = 0; j0 < NRES; j0 += 64) {
        for (int f = tid; f < 4096; f += 320) {
            int r = f >> 6, c = f & 63;
            float a = g_logits[((size_t)h * NRES + i0 + r) * NRES + j0 + c];
            sattn2[r][c] = make_float2(a, a);
        }
        for (int f = tid; f < 1280; f += 320)
            svp[f] = __ldg((const ull*)(g_vpack2 + ((size_t)h * NRES + j0) * 40) + f);
        __syncthreads();
#pragma unroll 4
        for (int jj = 0; jj < 64; jj++) {
            ull a2 = *(const ull*)&sattn2[il][jj];
            const ulonglong2* wv = (const ulonglong2*)&svp[jj * 20 + dg * 4];
            ulonglong2 w01 = wv[0], w23 = wv[1];
            fma2(acc[0], a2, w01.x); fma2(acc[1], a2, w01.y);
            fma2(acc[2], a2, w23.x); fma2(acc[3], a2, w23.y);
        }
        __syncthreads();
    }
    int n_i = i0 + il;
    float v[8];
#pragma unroll
    for (int q = 0; q < 4; q++) {
        float2 t = upk(acc[q]);
        v[2 * q] = t.x; v[2 * q + 1] = t.y;
    }
    if (dg < 2) {
        float* dst = g_final + (size_t)n_i * FINALD + h * 16 + dg * 8;
#pragma unroll
        for (int t = 0; t < 8; t++) dst[t] = v[t];
    } else {
        int d0 = (dg - 2) * 8;
#pragma unroll
        for (int t = 0; t < 8; t++) srpg[il][d0 + t] = v[t];
    }
    __syncthreads();
    for (int f = tid; f < 512; f += 320) {
        int ii = f >> 3, p = f & 7;
        int n = i0 + ii;
        float vx = srpg[ii][p * 3 + 0] - trans[n * 3 + 0];
        float vy = srpg[ii][p * 3 + 1] - trans[n * 3 + 1];
        float vz = srpg[ii][p * 3 + 2] - trans[n * 3 + 2];
        float nn = 1e-8f;
#pragma unroll
        for (int ic = 0; ic < 3; ic++) {
            float rl = rot[n * 9 + 0 + ic] * vx + rot[n * 9 + 3 + ic] * vy + rot[n * 9 + 6 + ic] * vz;
            g_final[(size_t)n * FINALD + 192 + ic * 96 + h * 8 + p] = rl;
            nn += rl * rl;
        }
        g_final[(size_t)n * FINALD + 480 + h * 8 + p] = sqrtf(nn);
    }
}

// ---------------- K5: output GEMM 768x384, K=2112, split-K=3 (f32x2) --------
__global__ __launch_bounds__(256) void k5_out(const float* __restrict__ out_w) {
    __shared__ float sA[32][65];
    __shared__ ull sB2[32][32];
    int tid = threadIdx.x, tx = tid & 15, ty = tid >> 4;
    int m0 = blockIdx.y * 64, n0 = blockIdx.x * 64;
    int kb = blockIdx.z * 704;
    ull acc[4][2] = {};
    for (int k0 = kb; k0 < kb + 704; k0 += 32) {
        for (int idx = tid; idx < 64 * 32; idx += 256) {
            int m = idx >> 5, kk = idx & 31;
            sA[kk][m] = g_final[(size_t)(m0 + m) * FINALD + k0 + kk];
        }
        for (int idx = tid; idx < 32 * 32; idx += 256) {
            int kk = idx >> 5, op = idx & 31;
            float2 wv = *(const float2*)(out_w + (size_t)(k0 + kk) * OUTD + n0 + op * 2);
            sB2[kk][op] = pk2two(wv.x, wv.y);
        }
        __syncthreads();
#pragma unroll
        for (int kk = 0; kk < 32; kk++) {
            ulonglong2 b01 = *(const ulonglong2*)&sB2[kk][tx * 2];
#pragma unroll
            for (int r = 0; r < 4; r++) {
                ull a2 = pk2(sA[kk][ty * 4 + r]);
                fma2(acc[r][0], a2, b01.x);
                fma2(acc[r][1], a2, b01.y);
            }
        }
        __syncthreads();
    }
#pragma unroll
    for (int r = 0; r < 4; r++) {
        int m = m0 + ty * 4 + r, o = n0 + tx * 4;
        float2 lo = upk(acc[r][0]), hi = upk(acc[r][1]);
        *(float4*)(g_part[blockIdx.z] + (size_t)m * OUTD + o) =
            make_float4(lo.x, lo.y, hi.x, hi.y);
    }
}

__global__ void k5r_reduce(const float* __restrict__ out_b, float* __restrict__ out) {
    int idx = blockIdx.x * 256 + threadIdx.x;
    if (idx < NRES * OUTD) {
        out[idx] = g_part[0][idx] + g_part[1][idx] + g_part[2][idx] + out_b[idx % OUTD];
    }
}

// ---------------- launch ----------------------------------------------------
extern "C" void kernel_launch(void* const* d_in, const int* in_sizes, int n_in,
                              void* d_out, int out_size) {
    const float* in1d  = (const float*)d_in[0];
    const float* in2d  = (const float*)d_in[1];
    const float* rot   = (const float*)d_in[2];
    const float* trans = (const float*)d_in[3];
    const float* qw    = (const float*)d_in[4];
    const float* qb    = (const float*)d_in[5];
    const float* kvw   = (const float*)d_in[6];
    const float* kvb   = (const float*)d_in[7];
    const float* qpw   = (const float*)d_in[8];
    const float* qpb   = (const float*)d_in[9];
    const float* kvpw  = (const float*)d_in[10];
    const float* kvpb  = (const float*)d_in[11];
    const float* tpw   = (const float*)d_in[12];
    const float* w2d   = (const float*)d_in[13];
    const float* b2d   = (const float*)d_in[14];
    const float* ow    = (const float*)d_in[15];
    const float* ob    = (const float*)d_in[16];
    float* out = (float*)d_out;

    cudaFuncSetAttribute(k4a_aover, cudaFuncAttributeMaxDynamicSharedMemorySize, K4A_SMEM);

    k0_prep<<<1728, 256>>>(qw, qb, kvw, kvb, qpw, qpb, kvpw, kvpb, tpw);
    k1a_gemm<<<dim3(18, 12), 256>>>(in1d);
    k1b_pack<<<768, 256>>>(rot, trans);
    k2_a2d<<<2304, 256>>>(in2d, w2d, b2d);
    k3_softmax<<<dim3(96, 12), 256>>>();
    k4a_aover<<<768, 256, K4A_SMEM>>>(in2d);
    k4b_vattend<<<dim3(12, 12), 320>>>(rot, trans);
    k5_out<<<dim3(6, 12, 3), 256>>>(ow);
    k5r_reduce<<<1152, 256>>>(ob, out);
}

// round 10
// speedup vs baseline: 2.0926x; 1.0289x over previous
#include <cuda_runtime.h>
#include <math.h>

#define NRES 768
#define MSAD 384
#define NH 12
#define PAIRD 128
#define OUTD 384
#define PROJ 1152
#define FINALD 2112

typedef unsigned long long ull;

// ---------------- f32x2 helpers (Blackwell packed fp32) ---------------------
__device__ __forceinline__ ull pk2(float v) {
    ull r; asm("mov.b64 %0, {%1, %1};" : "=l"(r) : "f"(v)); return r;
}
__device__ __forceinline__ ull pk2two(float lo, float hi) {
    ull r; asm("mov.b64 %0, {%1, %2};" : "=l"(r) : "f"(lo), "f"(hi)); return r;
}
__device__ __forceinline__ void fma2(ull& d, ull a, ull b) {
    asm("fma.rn.f32x2 %0, %1, %2, %0;" : "+l"(d) : "l"(a), "l"(b));
}
__device__ __forceinline__ void add2(ull& d, ull b) {
    asm("add.rn.f32x2 %0, %0, %1;" : "+l"(d) : "l"(b));
}
__device__ __forceinline__ float2 upk(ull v) {
    float2 r; asm("mov.b64 {%0, %1}, %2;" : "=f"(r.x), "=f"(r.y) : "l"(v)); return r;
}
// ---------------- cp.async helpers ------------------------------------------
__device__ __forceinline__ void cp16(void* dst, const void* src) {
    unsigned d = (unsigned)__cvta_generic_to_shared(dst);
    asm volatile("cp.async.cg.shared.global [%0], [%1], 16;" :: "r"(d), "l"(src));
}
__device__ __forceinline__ void cp_commit() {
    asm volatile("cp.async.commit_group;" ::: "memory");
}
__device__ __forceinline__ void cp_wait2() {
    asm volatile("cp.async.wait_group 2;" ::: "memory");
}

// ---------------- scratch (device globals; no allocation allowed) ----------
__device__ float g_wcat[MSAD * PROJ];
__device__ float g_bcat[PROJ];
__device__ float g_pw[NH];
__device__ float g_proj[NRES * PROJ];
__device__ float g_qpack[NH * NRES * 28];
__device__ float g_kpackT[NH * 32 * NRES];  // [h][d][j], d-major (d28 = bias)
__device__ float g_vpack2[NH * NRES * 40];
__device__ float g_logits[NH * NRES * NRES]; // a2d (k2) -> attn (k3)
__device__ float g_final[NRES * FINALD];
__device__ float g_part[3][NRES * OUTD];

// ---------------- K0 --------------------------------------------------------
__global__ void k0_prep(const float* __restrict__ qw, const float* __restrict__ qb,
                        const float* __restrict__ kvw, const float* __restrict__ kvb,
                        const float* __restrict__ qpw, const float* __restrict__ qpb,
                        const float* __restrict__ kvpw, const float* __restrict__ kvpb,
                        const float* __restrict__ tpw) {
    int idx = blockIdx.x * blockDim.x + threadIdx.x;
    if (idx < MSAD * PROJ) {
        int k = idx / PROJ, o = idx % PROJ;
        float v;
        if (o < 192)      v = qw[k * 192 + o];
        else if (o < 576) v = kvw[k * 384 + (o - 192)];
        else if (o < 720) v = qpw[k * 144 + (o - 576)];
        else              v = kvpw[k * 432 + (o - 720)];
        g_wcat[idx] = v;
    }
    if (idx < PROJ) {
        float b;
        if (idx < 192)      b = qb[idx];
        else if (idx < 576) b = kvb[idx - 192];
        else if (idx < 720) b = qpb[idx - 576];
        else                b = kvpb[idx - 720];
        g_bcat[idx] = b;
    }
    if (idx < NH) {
        float x = tpw[idx];
        float sp = (x > 20.f) ? x : log1pf(__expf(x));
        g_pw[idx] = sp * 0.13608276348795434f; // sqrt(1/54)
    }
}

// ---------------- K1a: projection GEMM 768x1152x384 (f32x2) -----------------
__global__ __launch_bounds__(256) void k1a_gemm(const float* __restrict__ in1d) {
    __shared__ float sA[32][65];
    __shared__ ull sB2[32][32];
    int tid = threadIdx.x;
    int tx = tid & 15, ty = tid >> 4;
    int m0 = blockIdx.y * 64, n0 = blockIdx.x * 64;
    ull acc[4][2] = {};
    for (int k0 = 0; k0 < MSAD; k0 += 32) {
        for (int idx = tid; idx < 64 * 32; idx += 256) {
            int m = idx >> 5, kk = idx & 31;
            sA[kk][m] = in1d[(m0 + m) * MSAD + k0 + kk];
        }
        for (int idx = tid; idx < 32 * 32; idx += 256) {
            int kk = idx >> 5, op = idx & 31;
            float2 w = *(const float2*)(g_wcat + (size_t)(k0 + kk) * PROJ + n0 + op * 2);
            sB2[kk][op] = pk2two(w.x, w.y);
        }
        __syncthreads();
#pragma unroll
        for (int kk = 0; kk < 32; kk++) {
            ulonglong2 b01 = *(const ulonglong2*)&sB2[kk][tx * 2];
#pragma unroll
            for (int r = 0; r < 4; r++) {
                ull a2 = pk2(sA[kk][ty * 4 + r]);
                fma2(acc[r][0], a2, b01.x);
                fma2(acc[r][1], a2, b01.y);
            }
        }
        __syncthreads();
    }
#pragma unroll
    for (int r = 0; r < 4; r++) {
        int m = m0 + ty * 4 + r, o = n0 + tx * 4;
        float2 lo = upk(acc[r][0]), hi = upk(acc[r][1]);
        g_proj[(size_t)m * PROJ + o + 0] = lo.x + g_bcat[o + 0];
        g_proj[(size_t)m * PROJ + o + 1] = lo.y + g_bcat[o + 1];
        g_proj[(size_t)m * PROJ + o + 2] = hi.x + g_bcat[o + 2];
        g_proj[(size_t)m * PROJ + o + 3] = hi.y + g_bcat[o + 3];
    }
}

// ---------------- K1b: apply rotations, pack q/k/v --------------------------
__global__ __launch_bounds__(256) void k1b_pack(const float* __restrict__ rot,
                                                const float* __restrict__ trans) {
    __shared__ float sp[PROJ];
    __shared__ float srot[9], strans[3], spw[12];
    __shared__ float sg[192 * 3];
    int n = blockIdx.x, tid = threadIdx.x;
    for (int t = tid; t < PROJ; t += 256) sp[t] = g_proj[n * PROJ + t];
    if (tid < 9) srot[tid] = rot[n * 9 + tid];
    if (tid < 3) strans[tid] = trans[n * 3 + tid];
    if (tid < 12) spw[tid] = g_pw[tid];
    __syncthreads();

    if (tid < 192) {
        int h = tid >> 4, d = tid & 15;
        g_qpack[(h * NRES + n) * 28 + d] = sp[tid] * 0.14433756729740643f; // 1/sqrt(48)
    }
    for (int t = tid; t < 384; t += 256) {
        int h = t >> 5, d = t & 31;
        if (d < 16) g_kpackT[((size_t)h * 32 + d) * NRES + n] = sp[192 + t];
        else        g_vpack2[((size_t)h * NRES + n) * 40 + (d - 16)] = sp[192 + t];
    }
    if (tid < 192) {
        float l0, l1, l2;
        if (tid < 48) { l0 = sp[576 + tid]; l1 = sp[576 + 48 + tid]; l2 = sp[576 + 96 + tid]; }
        else { int vs = tid - 48; l0 = sp[720 + vs]; l1 = sp[720 + 144 + vs]; l2 = sp[720 + 288 + vs]; }
#pragma unroll
        for (int c = 0; c < 3; c++)
            sg[tid * 3 + c] = srot[c * 3 + 0] * l0 + srot[c * 3 + 1] * l1 + srot[c * 3 + 2] * l2 + strans[c];
    }
    __syncthreads();
    if (tid < 48) {
        int h = tid >> 2, p = tid & 3;
        float pw = spw[h];
#pragma unroll
        for (int c = 0; c < 3; c++)
            g_qpack[(h * NRES + n) * 28 + 16 + p * 3 + c] = pw * sg[tid * 3 + c];
    } else if (tid < 192) {
        int vs = tid - 48, h = vs / 12, s = vs % 12;
        if (s < 4) {
#pragma unroll
            for (int c = 0; c < 3; c++)
                g_kpackT[((size_t)h * 32 + 16 + s * 3 + c) * NRES + n] = sg[tid * 3 + c];
        } else {
#pragma unroll
            for (int c = 0; c < 3; c++)
                g_vpack2[((size_t)h * NRES + n) * 40 + 16 + (s - 4) * 3 + c] = sg[tid * 3 + c];
        }
    }
    if (tid >= 192 && tid < 204) {
        int h = tid - 192;
        float s2 = 0.f;
        for (int s = 0; s < 4; s++)
            for (int c = 0; c < 3; c++) {
                float v = sg[(48 + h * 12 + s) * 3 + c];
                s2 += v * v;
            }
        g_kpackT[((size_t)h * 32 + 28) * NRES + n] = -0.5f * spw[h] * s2;
    }
}

// ---------------- K2: a2d GEMM, reg ping-pong + vector smem (pitch 20) ------
__global__ __launch_bounds__(256) void k2_a2d(const float* __restrict__ in2d,
                                              const float* __restrict__ w2d,
                                              const float* __restrict__ b2d) {
    __shared__ float sA[256 * 20];
    __shared__ ull sw2[128 * 6];
    __shared__ float sb[12];
    int tid = threadIdx.x;
    for (int f = tid; f < 128 * 6; f += 256) {
        int c = f / 6, hp = f % 6;
        float2 w = *(const float2*)(w2d + c * 12 + hp * 2);
        sw2[f] = pk2two(w.x, w.y);
    }
    if (tid < 12) sb[tid] = b2d[tid];
    size_t p0 = (size_t)blockIdx.x * 256;
    const float* src = in2d + p0 * PAIRD;

    // preload chunk 0 into staging regs (4 float4/thread)
    float4 st[4];
#pragma unroll
    for (int t = 0; t < 4; t++) {
        int f = tid + t * 256;            // 0..1023
        int r = f >> 2, c4 = f & 3;
        st[t] = __ldg((const float4*)(src + (size_t)r * PAIRD) + c4);
    }
    ull acc[6] = {};
#pragma unroll
    for (int ck = 0; ck < 8; ck++) {
        // vector store of staged regs (pitch 20 keeps LDS.128 conflict-free)
#pragma unroll
        for (int t = 0; t < 4; t++) {
            int f = tid + t * 256;
            int r = f >> 2, c4 = f & 3;
            *(float4*)&sA[r * 20 + c4 * 4] = st[t];
        }
        __syncthreads();
        // issue next chunk's loads (overlap with compute below)
        if (ck + 1 < 8) {
#pragma unroll
            for (int t = 0; t < 4; t++) {
                int f = tid + t * 256;
                int r = f >> 2, c4 = f & 3;
                st[t] = __ldg((const float4*)(src + (size_t)r * PAIRD + (ck + 1) * 16) + c4);
            }
        }
        const float4* A4 = (const float4*)&sA[tid * 20];
#pragma unroll
        for (int k4 = 0; k4 < 4; k4++) {
            float4 a = A4[k4];
#pragma unroll
            for (int q = 0; q < 4; q++) {
                float av = (q == 0) ? a.x : (q == 1) ? a.y : (q == 2) ? a.z : a.w;
                ull a2 = pk2(av);
                const ull* w = &sw2[(ck * 16 + k4 * 4 + q) * 6];
                ulonglong2 w01 = *(const ulonglong2*)(w + 0);
                ulonglong2 w23 = *(const ulonglong2*)(w + 2);
                ulonglong2 w45 = *(const ulonglong2*)(w + 4);
                fma2(acc[0], a2, w01.x); fma2(acc[1], a2, w01.y);
                fma2(acc[2], a2, w23.x); fma2(acc[3], a2, w23.y);
                fma2(acc[4], a2, w45.x); fma2(acc[5], a2, w45.y);
            }
        }
        __syncthreads();
    }
    size_t p = p0 + tid;
    int i = (int)(p / NRES), j = (int)(p % NRES);
    float res[12];
#pragma unroll
    for (int hp = 0; hp < 6; hp++) {
        float2 v = upk(acc[hp]);
        res[2 * hp] = v.x; res[2 * hp + 1] = v.y;
    }
#pragma unroll
    for (int h = 0; h < 12; h++)
        g_logits[((size_t)h * NRES + i) * NRES + j] = (res[h] + sb[h]) * 0.5773502691896258f;
}

// ---------------- K3: qk logits (coalesced kpackT) + softmax ----------------
__global__ __launch_bounds__(256) void k3_softmax() {
    __shared__ float srow[8][NRES];
    __shared__ ull su2[8][14];
    int h = blockIdx.y, i0 = blockIdx.x * 8;
    int tid = threadIdx.x;
    for (int t = tid; t < 8 * 14; t += 256) {
        int i8 = t / 14, dp = t % 14;
        const float* qp = g_qpack + ((size_t)h * NRES + (i0 + i8)) * 28 + dp * 2;
        su2[i8][dp] = pk2two(qp[0], qp[1]);
    }
    __syncthreads();
    const float* kbase = g_kpackT + (size_t)h * 32 * NRES;
    for (int jj = 0; jj < 3; jj++) {
        int j = jj * 256 + tid;
        const float* kb = kbase + j;
        ull wr2[14];
#pragma unroll
        for (int dp = 0; dp < 14; dp++)
            wr2[dp] = pk2two(__ldg(kb + (size_t)(2 * dp) * NRES),
                             __ldg(kb + (size_t)(2 * dp + 1) * NRES));
        float bias = __ldg(kb + (size_t)28 * NRES);
#pragma unroll
        for (int i8 = 0; i8 < 8; i8++) {
            ull acc2 = 0;
#pragma unroll
            for (int dp = 0; dp < 14; dp++) fma2(acc2, su2[i8][dp], wr2[dp]);
            float2 t = upk(acc2);
            srow[i8][j] = t.x + t.y + bias
                        + g_logits[((size_t)h * NRES + (i0 + i8)) * NRES + j];
        }
    }
    __syncthreads();
    // warp w owns row w
    int w = tid >> 5, lane = tid & 31;
    float vals[24];
    float m = -1e30f;
#pragma unroll
    for (int t = 0; t < 24; t++) {
        vals[t] = srow[w][t * 32 + lane];
        m = fmaxf(m, vals[t]);
    }
#pragma unroll
    for (int o = 16; o > 0; o >>= 1) m = fmaxf(m, __shfl_xor_sync(~0u, m, o));
    float s = 0.f;
#pragma unroll
    for (int t = 0; t < 24; t++) {
        float e = __expf(vals[t] - m);
        vals[t] = e; s += e;
    }
#pragma unroll
    for (int o = 16; o > 0; o >>= 1) s += __shfl_xor_sync(~0u, s, o);
    float inv = 1.f / s;
    float* dst = g_logits + ((size_t)h * NRES + (i0 + w)) * NRES;
#pragma unroll
    for (int t = 0; t < 24; t++) dst[t * 32 + lane] = vals[t] * inv;
}

// ---------------- K4a: a_over_2d (cp.async; each element read once) ---------
// 256 threads: rg = tid>>6 (row quarter), cp = tid&63 (col pair).
// Each thread: 12 heads x its rows x its col pair. Cross-rg reduce at end.
// smem: sattnT float[768*12] @0 (36864), sbuf float[4][16*128] @36864 (32768)
#define K4A_SMEM 69632
__global__ __launch_bounds__(256) void k4a_aover(const float* __restrict__ in2d) {
    extern __shared__ char smraw[];
    float* sattnT = (float*)smraw;            // [j][12]
    float* sbuf   = (float*)(smraw + 36864);
    int i = blockIdx.x, tid = threadIdx.x;

    const float* src = in2d + (size_t)i * NRES * PAIRD;
    // prologue: issue stages 0..2
#pragma unroll
    for (int s = 0; s < 3; s++) {
#pragma unroll
        for (int t = 0; t < 2; t++) {
            int f = tid + t * 256;
            int r = f >> 5, c4 = f & 31;
            cp16(sbuf + s * 2048 + r * 128 + c4 * 4,
                 src + (size_t)(s * 16 + r) * PAIRD + c4 * 4);
        }
        cp_commit();
    }
    // transpose-load attention row: sattnT[j][h]
    for (int f = tid; f < 9216; f += 256) {
        int h = f / NRES, j = f % NRES;
        sattnT[j * 12 + h] = __ldg(g_logits + ((size_t)h * NRES + i) * NRES + j);
    }
    __syncthreads();

    int rg = tid >> 6, cp = tid & 63;
    ull acc[12] = {};

    for (int s = 0; s < 48; s++) {
        cp_wait2();
        __syncthreads();
        if (s + 3 < 48) {
            int sn = s + 3;
#pragma unroll
            for (int t = 0; t < 2; t++) {
                int f = tid + t * 256;
                int r = f >> 5, c4 = f & 31;
                cp16(sbuf + (sn & 3) * 2048 + r * 128 + c4 * 4,
                     src + (size_t)(sn * 16 + r) * PAIRD + c4 * 4);
            }
        }
        cp_commit();
        const ull* bb = (const ull*)(sbuf + (s & 3) * 2048);
        int j0 = s * 16;
#pragma unroll
        for (int r = 0; r < 4; r++) {
            int jl = rg * 4 + r;
            ull d = bb[jl * 64 + cp];
            const float4* ap = (const float4*)&sattnT[(j0 + jl) * 12];
            float4 a0 = ap[0], a1 = ap[1], a2v = ap[2];
            fma2(acc[0], pk2(a0.x), d);  fma2(acc[1], pk2(a0.y), d);
            fma2(acc[2], pk2(a0.z), d);  fma2(acc[3], pk2(a0.w), d);
            fma2(acc[4], pk2(a1.x), d);  fma2(acc[5], pk2(a1.y), d);
            fma2(acc[6], pk2(a1.z), d);  fma2(acc[7], pk2(a1.w), d);
            fma2(acc[8], pk2(a2v.x), d); fma2(acc[9], pk2(a2v.y), d);
            fma2(acc[10], pk2(a2v.z), d); fma2(acc[11], pk2(a2v.w), d);
        }
    }
    // cross-rg reduction via smem (sbuf reusable; only empty groups pending)
    __syncthreads();
    ull* red = (ull*)sbuf;   // [256][13] ull = 26624 B <= 32768
#pragma unroll
    for (int h = 0; h < 12; h++) red[(rg * 64 + cp) * 13 + h] = acc[h];
    __syncthreads();
    for (int pi = tid; pi < 768; pi += 256) {
        int h = pi >> 6, c2 = pi & 63;
        ull t0 = red[(0 * 64 + c2) * 13 + h];
        add2(t0, red[(1 * 64 + c2) * 13 + h]);
        add2(t0, red[(2 * 64 + c2) * 13 + h]);
        add2(t0, red[(3 * 64 + c2) * 13 + h]);
        float2 v = upk(t0);
        *(float2*)(g_final + (size_t)i * FINALD + 576 + h * PAIRD + 2 * c2) = v;
    }
}

// ---------------- K4b: per-head GEMM for v / vp + rotate-back epilogue ------
__global__ __launch_bounds__(320) void k4b_vattend(const float* __restrict__ rot,
                                                   const float* __restrict__ trans) {
    __shared__ float2 sattn2[64][65];
    __shared__ ull svp[64 * 20];
    __shared__ float srpg[64][24];
    int i0 = blockIdx.x * 64, h = blockIdx.y;
    int tid = threadIdx.x, il = tid & 63, dg = tid >> 6;
    ull acc[4] = {};
    for (int j0 = 0; j0 < NRES; j0 += 64) {
        for (int f = tid; f < 4096; f += 320) {
            int r = f >> 6, c = f & 63;
            float a = g_logits[((size_t)h * NRES + i0 + r) * NRES + j0 + c];
            sattn2[r][c] = make_float2(a, a);
        }
        for (int f = tid; f < 1280; f += 320)
            svp[f] = __ldg((const ull*)(g_vpack2 + ((size_t)h * NRES + j0) * 40) + f);
        __syncthreads();
#pragma unroll 4
        for (int jj = 0; jj < 64; jj++) {
            ull a2 = *(const ull*)&sattn2[il][jj];
            const ulonglong2* wv = (const ulonglong2*)&svp[jj * 20 + dg * 4];
            ulonglong2 w01 = wv[0], w23 = wv[1];
            fma2(acc[0], a2, w01.x); fma2(acc[1], a2, w01.y);
            fma2(acc[2], a2, w23.x); fma2(acc[3], a2, w23.y);
        }
        __syncthreads();
    }
    int n_i = i0 + il;
    float v[8];
#pragma unroll
    for (int q = 0; q < 4; q++) {
        float2 t = upk(acc[q]);
        v[2 * q] = t.x; v[2 * q + 1] = t.y;
    }
    if (dg < 2) {
        float* dst = g_final + (size_t)n_i * FINALD + h * 16 + dg * 8;
#pragma unroll
        for (int t = 0; t < 8; t++) dst[t] = v[t];
    } else {
        int d0 = (dg - 2) * 8;
#pragma unroll
        for (int t = 0; t < 8; t++) srpg[il][d0 + t] = v[t];
    }
    __syncthreads();
    for (int f = tid; f < 512; f += 320) {
        int ii = f >> 3, p = f & 7;
        int n = i0 + ii;
        float vx = srpg[ii][p * 3 + 0] - trans[n * 3 + 0];
        float vy = srpg[ii][p * 3 + 1] - trans[n * 3 + 1];
        float vz = srpg[ii][p * 3 + 2] - trans[n * 3 + 2];
        float nn = 1e-8f;
#pragma unroll
        for (int ic = 0; ic < 3; ic++) {
            float rl = rot[n * 9 + 0 + ic] * vx + rot[n * 9 + 3 + ic] * vy + rot[n * 9 + 6 + ic] * vz;
            g_final[(size_t)n * FINALD + 192 + ic * 96 + h * 8 + p] = rl;
            nn += rl * rl;
        }
        g_final[(size_t)n * FINALD + 480 + h * 8 + p] = sqrtf(nn);
    }
}

// ---------------- K5: output GEMM 768x384, K=2112, split-K=3 (f32x2) --------
__global__ __launch_bounds__(256) void k5_out(const float* __restrict__ out_w) {
    __shared__ float sA[32][65];
    __shared__ ull sB2[32][32];
    int tid = threadIdx.x, tx = tid & 15, ty = tid >> 4;
    int m0 = blockIdx.y * 64, n0 = blockIdx.x * 64;
    int kb = blockIdx.z * 704;
    ull acc[4][2] = {};
    for (int k0 = kb; k0 < kb + 704; k0 += 32) {
        for (int idx = tid; idx < 64 * 32; idx += 256) {
            int m = idx >> 5, kk = idx & 31;
            sA[kk][m] = g_final[(size_t)(m0 + m) * FINALD + k0 + kk];
        }
        for (int idx = tid; idx < 32 * 32; idx += 256) {
            int kk = idx >> 5, op = idx & 31;
            float2 wv = *(const float2*)(out_w + (size_t)(k0 + kk) * OUTD + n0 + op * 2);
            sB2[kk][op] = pk2two(wv.x, wv.y);
        }
        __syncthreads();
#pragma unroll
        for (int kk = 0; kk < 32; kk++) {
            ulonglong2 b01 = *(const ulonglong2*)&sB2[kk][tx * 2];
#pragma unroll
            for (int r = 0; r < 4; r++) {
                ull a2 = pk2(sA[kk][ty * 4 + r]);
                fma2(acc[r][0], a2, b01.x);
                fma2(acc[r][1], a2, b01.y);
            }
        }
        __syncthreads();
    }
#pragma unroll
    for (int r = 0; r < 4; r++) {
        int m = m0 + ty * 4 + r, o = n0 + tx * 4;
        float2 lo = upk(acc[r][0]), hi = upk(acc[r][1]);
        *(float4*)(g_part[blockIdx.z] + (size_t)m * OUTD + o) =
            make_float4(lo.x, lo.y, hi.x, hi.y);
    }
}

__global__ void k5r_reduce(const float* __restrict__ out_b, float* __restrict__ out) {
    int idx = blockIdx.x * 256 + threadIdx.x;
    if (idx < NRES * OUTD) {
        out[idx] = g_part[0][idx] + g_part[1][idx] + g_part[2][idx] + out_b[idx % OUTD];
    }
}

// ---------------- launch ----------------------------------------------------
extern "C" void kernel_launch(void* const* d_in, const int* in_sizes, int n_in,
                              void* d_out, int out_size) {
    const float* in1d  = (const float*)d_in[0];
    const float* in2d  = (const float*)d_in[1];
    const float* rot   = (const float*)d_in[2];
    const float* trans = (const float*)d_in[3];
    const float* qw    = (const float*)d_in[4];
    const float* qb    = (const float*)d_in[5];
    const float* kvw   = (const float*)d_in[6];
    const float* kvb   = (const float*)d_in[7];
    const float* qpw   = (const float*)d_in[8];
    const float* qpb   = (const float*)d_in[9];
    const float* kvpw  = (const float*)d_in[10];
    const float* kvpb  = (const float*)d_in[11];
    const float* tpw   = (const float*)d_in[12];
    const float* w2d   = (const float*)d_in[13];
    const float* b2d   = (const float*)d_in[14];
    const float* ow    = (const float*)d_in[15];
    const float* ob    = (const float*)d_in[16];
    float* out = (float*)d_out;

    cudaFuncSetAttribute(k4a_aover, cudaFuncAttributeMaxDynamicSharedMemorySize, K4A_SMEM);

    k0_prep<<<1728, 256>>>(qw, qb, kvw, kvb, qpw, qpb, kvpw, kvpb, tpw);
    k1a_gemm<<<dim3(18, 12), 256>>>(in1d);
    k1b_pack<<<768, 256>>>(rot, trans);
    k2_a2d<<<2304, 256>>>(in2d, w2d, b2d);
    k3_softmax<<<dim3(96, 12), 256>>>();
    k4a_aover<<<768, 256, K4A_SMEM>>>(in2d);
    k4b_vattend<<<dim3(12, 12), 320>>>(rot, trans);
    k5_out<<<dim3(6, 12, 3), 256>>>(ow);
    k5r_reduce<<<1152, 256>>>(ob, out);
}

// round 11
// speedup vs baseline: 2.1630x; 1.0336x over previous
#include <cuda_runtime.h>
#include <math.h>

#define NRES 768
#define MSAD 384
#define NH 12
#define PAIRD 128
#define OUTD 384
#define PROJ 1152
#define FINALD 2112

typedef unsigned long long ull;

// ---------------- f32x2 helpers (Blackwell packed fp32) ---------------------
__device__ __forceinline__ ull pk2(float v) {
    ull r; asm("mov.b64 %0, {%1, %1};" : "=l"(r) : "f"(v)); return r;
}
__device__ __forceinline__ ull pk2two(float lo, float hi) {
    ull r; asm("mov.b64 %0, {%1, %2};" : "=l"(r) : "f"(lo), "f"(hi)); return r;
}
__device__ __forceinline__ void fma2(ull& d, ull a, ull b) {
    asm("fma.rn.f32x2 %0, %1, %2, %0;" : "+l"(d) : "l"(a), "l"(b));
}
__device__ __forceinline__ void add2(ull& d, ull b) {
    asm("add.rn.f32x2 %0, %0, %1;" : "+l"(d) : "l"(b));
}
__device__ __forceinline__ float2 upk(ull v) {
    float2 r; asm("mov.b64 {%0, %1}, %2;" : "=f"(r.x), "=f"(r.y) : "l"(v)); return r;
}
// ---------------- cp.async helpers ------------------------------------------
__device__ __forceinline__ void cp16(void* dst, const void* src) {
    unsigned d = (unsigned)__cvta_generic_to_shared(dst);
    asm volatile("cp.async.cg.shared.global [%0], [%1], 16;" :: "r"(d), "l"(src));
}
__device__ __forceinline__ void cp_commit() {
    asm volatile("cp.async.commit_group;" ::: "memory");
}
__device__ __forceinline__ void cp_wait2() {
    asm volatile("cp.async.wait_group 2;" ::: "memory");
}

// ---------------- scratch (device globals; no allocation allowed) ----------
__device__ float g_wcat[MSAD * PROJ];
__device__ float g_bcat[PROJ];
__device__ float g_pw[NH];
__device__ float g_proj[NRES * PROJ];
__device__ float g_qpack[NH * NRES * 28];
__device__ float g_kpackT[NH * 32 * NRES];  // [h][d][j], d-major (d28 = bias)
__device__ float g_vpack2[NH * NRES * 40];
__device__ float g_logits[NH * NRES * NRES]; // a2d (k2) -> attn (k3)
__device__ float g_final[NRES * FINALD];
__device__ float g_part[3][NRES * OUTD];

// ---------------- K0 --------------------------------------------------------
__global__ void k0_prep(const float* __restrict__ qw, const float* __restrict__ qb,
                        const float* __restrict__ kvw, const float* __restrict__ kvb,
                        const float* __restrict__ qpw, const float* __restrict__ qpb,
                        const float* __restrict__ kvpw, const float* __restrict__ kvpb,
                        const float* __restrict__ tpw) {
    int idx = blockIdx.x * blockDim.x + threadIdx.x;
    if (idx < MSAD * PROJ) {
        int k = idx / PROJ, o = idx % PROJ;
        float v;
        if (o < 192)      v = qw[k * 192 + o];
        else if (o < 576) v = kvw[k * 384 + (o - 192)];
        else if (o < 720) v = qpw[k * 144 + (o - 576)];
        else              v = kvpw[k * 432 + (o - 720)];
        g_wcat[idx] = v;
    }
    if (idx < PROJ) {
        float b;
        if (idx < 192)      b = qb[idx];
        else if (idx < 576) b = kvb[idx - 192];
        else if (idx < 720) b = qpb[idx - 576];
        else                b = kvpb[idx - 720];
        g_bcat[idx] = b;
    }
    if (idx < NH) {
        float x = tpw[idx];
        float sp = (x > 20.f) ? x : log1pf(__expf(x));
        g_pw[idx] = sp * 0.13608276348795434f; // sqrt(1/54)
    }
}

// ---------------- K1a: projection GEMM 768x1152x384 (f32x2) -----------------
__global__ __launch_bounds__(256) void k1a_gemm(const float* __restrict__ in1d) {
    __shared__ float sA[32][65];
    __shared__ ull sB2[32][32];
    int tid = threadIdx.x;
    int tx = tid & 15, ty = tid >> 4;
    int m0 = blockIdx.y * 64, n0 = blockIdx.x * 64;
    ull acc[4][2] = {};
    for (int k0 = 0; k0 < MSAD; k0 += 32) {
        for (int idx = tid; idx < 64 * 32; idx += 256) {
            int m = idx >> 5, kk = idx & 31;
            sA[kk][m] = in1d[(m0 + m) * MSAD + k0 + kk];
        }
        for (int idx = tid; idx < 32 * 32; idx += 256) {
            int kk = idx >> 5, op = idx & 31;
            float2 w = *(const float2*)(g_wcat + (size_t)(k0 + kk) * PROJ + n0 + op * 2);
            sB2[kk][op] = pk2two(w.x, w.y);
        }
        __syncthreads();
#pragma unroll
        for (int kk = 0; kk < 32; kk++) {
            ulonglong2 b01 = *(const ulonglong2*)&sB2[kk][tx * 2];
#pragma unroll
            for (int r = 0; r < 4; r++) {
                ull a2 = pk2(sA[kk][ty * 4 + r]);
                fma2(acc[r][0], a2, b01.x);
                fma2(acc[r][1], a2, b01.y);
            }
        }
        __syncthreads();
    }
#pragma unroll
    for (int r = 0; r < 4; r++) {
        int m = m0 + ty * 4 + r, o = n0 + tx * 4;
        float2 lo = upk(acc[r][0]), hi = upk(acc[r][1]);
        g_proj[(size_t)m * PROJ + o + 0] = lo.x + g_bcat[o + 0];
        g_proj[(size_t)m * PROJ + o + 1] = lo.y + g_bcat[o + 1];
        g_proj[(size_t)m * PROJ + o + 2] = hi.x + g_bcat[o + 2];
        g_proj[(size_t)m * PROJ + o + 3] = hi.y + g_bcat[o + 3];
    }
}

// ---------------- K1b: apply rotations, pack q/k/v --------------------------
__global__ __launch_bounds__(256) void k1b_pack(const float* __restrict__ rot,
                                                const float* __restrict__ trans) {
    __shared__ float sp[PROJ];
    __shared__ float srot[9], strans[3], spw[12];
    __shared__ float sg[192 * 3];
    int n = blockIdx.x, tid = threadIdx.x;
    for (int t = tid; t < PROJ; t += 256) sp[t] = g_proj[n * PROJ + t];
    if (tid < 9) srot[tid] = rot[n * 9 + tid];
    if (tid < 3) strans[tid] = trans[n * 3 + tid];
    if (tid < 12) spw[tid] = g_pw[tid];
    __syncthreads();

    if (tid < 192) {
        int h = tid >> 4, d = tid & 15;
        g_qpack[(h * NRES + n) * 28 + d] = sp[tid] * 0.14433756729740643f; // 1/sqrt(48)
    }
    for (int t = tid; t < 384; t += 256) {
        int h = t >> 5, d = t & 31;
        if (d < 16) g_kpackT[((size_t)h * 32 + d) * NRES + n] = sp[192 + t];
        else        g_vpack2[((size_t)h * NRES + n) * 40 + (d - 16)] = sp[192 + t];
    }
    if (tid < 192) {
        float l0, l1, l2;
        if (tid < 48) { l0 = sp[576 + tid]; l1 = sp[576 + 48 + tid]; l2 = sp[576 + 96 + tid]; }
        else { int vs = tid - 48; l0 = sp[720 + vs]; l1 = sp[720 + 144 + vs]; l2 = sp[720 + 288 + vs]; }
#pragma unroll
        for (int c = 0; c < 3; c++)
            sg[tid * 3 + c] = srot[c * 3 + 0] * l0 + srot[c * 3 + 1] * l1 + srot[c * 3 + 2] * l2 + strans[c];
    }
    __syncthreads();
    if (tid < 48) {
        int h = tid >> 2, p = tid & 3;
        float pw = spw[h];
#pragma unroll
        for (int c = 0; c < 3; c++)
            g_qpack[(h * NRES + n) * 28 + 16 + p * 3 + c] = pw * sg[tid * 3 + c];
    } else if (tid < 192) {
        int vs = tid - 48, h = vs / 12, s = vs % 12;
        if (s < 4) {
#pragma unroll
            for (int c = 0; c < 3; c++)
                g_kpackT[((size_t)h * 32 + 16 + s * 3 + c) * NRES + n] = sg[tid * 3 + c];
        } else {
#pragma unroll
            for (int c = 0; c < 3; c++)
                g_vpack2[((size_t)h * NRES + n) * 40 + 16 + (s - 4) * 3 + c] = sg[tid * 3 + c];
        }
    }
    if (tid >= 192 && tid < 204) {
        int h = tid - 192;
        float s2 = 0.f;
        for (int s = 0; s < 4; s++)
            for (int c = 0; c < 3; c++) {
                float v = sg[(48 + h * 12 + s) * 3 + c];
                s2 += v * v;
            }
        g_kpackT[((size_t)h * 32 + 28) * NRES + n] = -0.5f * spw[h] * s2;
    }
}

// ---------------- K2: a2d GEMM, cp.async 3-buffer pipeline ------------------
// Stage = 16-col chunk x 256 rows, pitch 20 floats (80B: 16B-aligned for
// cp.async, LDS.128-conflict-free). 3 stages x 20KB + 6KB weights = 66KB.
// smem: sbuf @0 (61440), sw2 @61440 (6144), sb @67584
#define K2_SMEM 67648
__global__ __launch_bounds__(256) void k2_a2d(const float* __restrict__ in2d,
                                              const float* __restrict__ w2d,
                                              const float* __restrict__ b2d) {
    extern __shared__ char smraw[];
    float* sbuf = (float*)smraw;                 // [3][256*20]
    ull*   sw2  = (ull*)(smraw + 61440);
    float* sb   = (float*)(smraw + 67584);
    int tid = threadIdx.x;
    size_t p0 = (size_t)blockIdx.x * 256;
    const float* src = in2d + p0 * PAIRD;

    // prologue: issue chunks 0 and 1
#pragma unroll
    for (int s = 0; s < 2; s++) {
#pragma unroll
        for (int t = 0; t < 4; t++) {
            int f = tid + t * 256;          // 0..1023
            int r = f >> 2, c4 = f & 3;
            cp16(sbuf + s * 5120 + r * 20 + c4 * 4,
                 src + (size_t)r * PAIRD + s * 16 + c4 * 4);
        }
        cp_commit();
    }
    // stage weights (overlaps with in-flight cp.async)
    for (int f = tid; f < 128 * 6; f += 256) {
        int c = f / 6, hp = f % 6;
        float2 w = *(const float2*)(w2d + c * 12 + hp * 2);
        sw2[f] = pk2two(w.x, w.y);
    }
    if (tid < 12) sb[tid] = b2d[tid];

    ull acc[6] = {};
#pragma unroll
    for (int ck = 0; ck < 8; ck++) {
        // issue chunk ck+2 (buffer held chunk ck-1; freed by prev iter's sync)
        if (ck + 2 < 8) {
            int sn = ck + 2;
#pragma unroll
            for (int t = 0; t < 4; t++) {
                int f = tid + t * 256;
                int r = f >> 2, c4 = f & 3;
                cp16(sbuf + (sn % 3) * 5120 + r * 20 + c4 * 4,
                     src + (size_t)r * PAIRD + sn * 16 + c4 * 4);
            }
        }
        cp_commit();
        cp_wait2();          // <=2 outstanding -> chunk ck arrived
        __syncthreads();
        const float4* A4 = (const float4*)&sbuf[(ck % 3) * 5120 + tid * 20];
#pragma unroll
        for (int k4 = 0; k4 < 4; k4++) {
            float4 a = A4[k4];
#pragma unroll
            for (int q = 0; q < 4; q++) {
                float av = (q == 0) ? a.x : (q == 1) ? a.y : (q == 2) ? a.z : a.w;
                ull a2 = pk2(av);
                const ull* w = &sw2[(ck * 16 + k4 * 4 + q) * 6];
                ulonglong2 w01 = *(const ulonglong2*)(w + 0);
                ulonglong2 w23 = *(const ulonglong2*)(w + 2);
                ulonglong2 w45 = *(const ulonglong2*)(w + 4);
                fma2(acc[0], a2, w01.x); fma2(acc[1], a2, w01.y);
                fma2(acc[2], a2, w23.x); fma2(acc[3], a2, w23.y);
                fma2(acc[4], a2, w45.x); fma2(acc[5], a2, w45.y);
            }
        }
        __syncthreads();
    }
    size_t p = p0 + tid;
    int i = (int)(p / NRES), j = (int)(p % NRES);
    float res[12];
#pragma unroll
    for (int hp = 0; hp < 6; hp++) {
        float2 v = upk(acc[hp]);
        res[2 * hp] = v.x; res[2 * hp + 1] = v.y;
    }
#pragma unroll
    for (int h = 0; h < 12; h++)
        g_logits[((size_t)h * NRES + i) * NRES + j] = (res[h] + sb[h]) * 0.5773502691896258f;
}

// ---------------- K3: qk logits (coalesced kpackT) + softmax ----------------
__global__ __launch_bounds__(256) void k3_softmax() {
    __shared__ float srow[8][NRES];
    __shared__ ull su2[8][14];
    int h = blockIdx.y, i0 = blockIdx.x * 8;
    int tid = threadIdx.x;
    for (int t = tid; t < 8 * 14; t += 256) {
        int i8 = t / 14, dp = t % 14;
        const float* qp = g_qpack + ((size_t)h * NRES + (i0 + i8)) * 28 + dp * 2;
        su2[i8][dp] = pk2two(qp[0], qp[1]);
    }
    __syncthreads();
    const float* kbase = g_kpackT + (size_t)h * 32 * NRES;
    for (int jj = 0; jj < 3; jj++) {
        int j = jj * 256 + tid;
        const float* kb = kbase + j;
        ull wr2[14];
#pragma unroll
        for (int dp = 0; dp < 14; dp++)
            wr2[dp] = pk2two(__ldg(kb + (size_t)(2 * dp) * NRES),
                             __ldg(kb + (size_t)(2 * dp + 1) * NRES));
        float bias = __ldg(kb + (size_t)28 * NRES);
#pragma unroll
        for (int i8 = 0; i8 < 8; i8++) {
            ull acc2 = 0;
#pragma unroll
            for (int dp = 0; dp < 14; dp++) fma2(acc2, su2[i8][dp], wr2[dp]);
            float2 t = upk(acc2);
            srow[i8][j] = t.x + t.y + bias
                        + g_logits[((size_t)h * NRES + (i0 + i8)) * NRES + j];
        }
    }
    __syncthreads();
    // warp w owns row w
    int w = tid >> 5, lane = tid & 31;
    float vals[24];
    float m = -1e30f;
#pragma unroll
    for (int t = 0; t < 24; t++) {
        vals[t] = srow[w][t * 32 + lane];
        m = fmaxf(m, vals[t]);
    }
#pragma unroll
    for (int o = 16; o > 0; o >>= 1) m = fmaxf(m, __shfl_xor_sync(~0u, m, o));
    float s = 0.f;
#pragma unroll
    for (int t = 0; t < 24; t++) {
        float e = __expf(vals[t] - m);
        vals[t] = e; s += e;
    }
#pragma unroll
    for (int o = 16; o > 0; o >>= 1) s += __shfl_xor_sync(~0u, s, o);
    float inv = 1.f / s;
    float* dst = g_logits + ((size_t)h * NRES + (i0 + w)) * NRES;
#pragma unroll
    for (int t = 0; t < 24; t++) dst[t * 32 + lane] = vals[t] * inv;
}

// ---------------- K4a: a_over_2d (cp.async; each element read once) ---------
// 256 threads: rg = tid>>6 (row quarter), cp = tid&63 (col pair).
// smem: sattnT float[768*12] @0 (36864), sbuf float[4][16*128] @36864 (32768)
#define K4A_SMEM 69632
__global__ __launch_bounds__(256) void k4a_aover(const float* __restrict__ in2d) {
    extern __shared__ char smraw[];
    float* sattnT = (float*)smraw;            // [j][12]
    float* sbuf   = (float*)(smraw + 36864);
    int i = blockIdx.x, tid = threadIdx.x;

    const float* src = in2d + (size_t)i * NRES * PAIRD;
#pragma unroll
    for (int s = 0; s < 3; s++) {
#pragma unroll
        for (int t = 0; t < 2; t++) {
            int f = tid + t * 256;
            int r = f >> 5, c4 = f & 31;
            cp16(sbuf + s * 2048 + r * 128 + c4 * 4,
                 src + (size_t)(s * 16 + r) * PAIRD + c4 * 4);
        }
        cp_commit();
    }
    for (int f = tid; f < 9216; f += 256) {
        int h = f / NRES, j = f % NRES;
        sattnT[j * 12 + h] = __ldg(g_logits + ((size_t)h * NRES + i) * NRES + j);
    }
    __syncthreads();

    int rg = tid >> 6, cp = tid & 63;
    ull acc[12] = {};

    for (int s = 0; s < 48; s++) {
        cp_wait2();
        __syncthreads();
        if (s + 3 < 48) {
            int sn = s + 3;
#pragma unroll
            for (int t = 0; t < 2; t++) {
                int f = tid + t * 256;
                int r = f >> 5, c4 = f & 31;
                cp16(sbuf + (sn & 3) * 2048 + r * 128 + c4 * 4,
                     src + (size_t)(sn * 16 + r) * PAIRD + c4 * 4);
            }
        }
        cp_commit();
        const ull* bb = (const ull*)(sbuf + (s & 3) * 2048);
        int j0 = s * 16;
#pragma unroll
        for (int r = 0; r < 4; r++) {
            int jl = rg * 4 + r;
            ull d = bb[jl * 64 + cp];
            const float4* ap = (const float4*)&sattnT[(j0 + jl) * 12];
            float4 a0 = ap[0], a1 = ap[1], a2v = ap[2];
            fma2(acc[0], pk2(a0.x), d);  fma2(acc[1], pk2(a0.y), d);
            fma2(acc[2], pk2(a0.z), d);  fma2(acc[3], pk2(a0.w), d);
            fma2(acc[4], pk2(a1.x), d);  fma2(acc[5], pk2(a1.y), d);
            fma2(acc[6], pk2(a1.z), d);  fma2(acc[7], pk2(a1.w), d);
            fma2(acc[8], pk2(a2v.x), d); fma2(acc[9], pk2(a2v.y), d);
            fma2(acc[10], pk2(a2v.z), d); fma2(acc[11], pk2(a2v.w), d);
        }
    }
    __syncthreads();
    ull* red = (ull*)sbuf;   // [256][13] ull = 26624 B <= 32768
#pragma unroll
    for (int h = 0; h < 12; h++) red[(rg * 64 + cp) * 13 + h] = acc[h];
    __syncthreads();
    for (int pi = tid; pi < 768; pi += 256) {
        int h = pi >> 6, c2 = pi & 63;
        ull t0 = red[(0 * 64 + c2) * 13 + h];
        add2(t0, red[(1 * 64 + c2) * 13 + h]);
        add2(t0, red[(2 * 64 + c2) * 13 + h]);
        add2(t0, red[(3 * 64 + c2) * 13 + h]);
        float2 v = upk(t0);
        *(float2*)(g_final + (size_t)i * FINALD + 576 + h * PAIRD + 2 * c2) = v;
    }
}

// ---------------- K4b: per-head GEMM for v / vp + rotate-back epilogue ------
__global__ __launch_bounds__(320) void k4b_vattend(const float* __restrict__ rot,
                                                   const float* __restrict__ trans) {
    __shared__ float2 sattn2[64][65];
    __shared__ ull svp[64 * 20];
    __shared__ float srpg[64][24];
    int i0 = blockIdx.x * 64, h = blockIdx.y;
    int tid = threadIdx.x, il = tid & 63, dg = tid >> 6;
    ull acc[4] = {};
    for (int j0 = 0; j0 < NRES; j0 += 64) {
        for (int f = tid; f < 4096; f += 320) {
            int r = f >> 6, c = f & 63;
            float a = g_logits[((size_t)h * NRES + i0 + r) * NRES + j0 + c];
            sattn2[r][c] = make_float2(a, a);
        }
        for (int f = tid; f < 1280; f += 320)
            svp[f] = __ldg((const ull*)(g_vpack2 + ((size_t)h * NRES + j0) * 40) + f);
        __syncthreads();
#pragma unroll 4
        for (int jj = 0; jj < 64; jj++) {
            ull a2 = *(const ull*)&sattn2[il][jj];
            const ulonglong2* wv = (const ulonglong2*)&svp[jj * 20 + dg * 4];
            ulonglong2 w01 = wv[0], w23 = wv[1];
            fma2(acc[0], a2, w01.x); fma2(acc[1], a2, w01.y);
            fma2(acc[2], a2, w23.x); fma2(acc[3], a2, w23.y);
        }
        __syncthreads();
    }
    int n_i = i0 + il;
    float v[8];
#pragma unroll
    for (int q = 0; q < 4; q++) {
        float2 t = upk(acc[q]);
        v[2 * q] = t.x; v[2 * q + 1] = t.y;
    }
    if (dg < 2) {
        float* dst = g_final + (size_t)n_i * FINALD + h * 16 + dg * 8;
#pragma unroll
        for (int t = 0; t < 8; t++) dst[t] = v[t];
    } else {
        int d0 = (dg - 2) * 8;
#pragma unroll
        for (int t = 0; t < 8; t++) srpg[il][d0 + t] = v[t];
    }
    __syncthreads();
    for (int f = tid; f < 512; f += 320) {
        int ii = f >> 3, p = f & 7;
        int n = i0 + ii;
        float vx = srpg[ii][p * 3 + 0] - trans[n * 3 + 0];
        float vy = srpg[ii][p * 3 + 1] - trans[n * 3 + 1];
        float vz = srpg[ii][p * 3 + 2] - trans[n * 3 + 2];
        float nn = 1e-8f;
#pragma unroll
        for (int ic = 0; ic < 3; ic++) {
            float rl = rot[n * 9 + 0 + ic] * vx + rot[n * 9 + 3 + ic] * vy + rot[n * 9 + 6 + ic] * vz;
            g_final[(size_t)n * FINALD + 192 + ic * 96 + h * 8 + p] = rl;
            nn += rl * rl;
        }
        g_final[(size_t)n * FINALD + 480 + h * 8 + p] = sqrtf(nn);
    }
}

// ---------------- K5: output GEMM 768x384, K=2112, split-K=3 (f32x2) --------
__global__ __launch_bounds__(256) void k5_out(const float* __restrict__ out_w) {
    __shared__ float sA[32][65];
    __shared__ ull sB2[32][32];
    int tid = threadIdx.x, tx = tid & 15, ty = tid >> 4;
    int m0 = blockIdx.y * 64, n0 = blockIdx.x * 64;
    int kb = blockIdx.z * 704;
    ull acc[4][2] = {};
    for (int k0 = kb; k0 < kb + 704; k0 += 32) {
        for (int idx = tid; idx < 64 * 32; idx += 256) {
            int m = idx >> 5, kk = idx & 31;
            sA[kk][m] = g_final[(size_t)(m0 + m) * FINALD + k0 + kk];
        }
        for (int idx = tid; idx < 32 * 32; idx += 256) {
            int kk = idx >> 5, op = idx & 31;
            float2 wv = *(const float2*)(out_w + (size_t)(k0 + kk) * OUTD + n0 + op * 2);
            sB2[kk][op] = pk2two(wv.x, wv.y);
        }
        __syncthreads();
#pragma unroll
        for (int kk = 0; kk < 32; kk++) {
            ulonglong2 b01 = *(const ulonglong2*)&sB2[kk][tx * 2];
#pragma unroll
            for (int r = 0; r < 4; r++) {
                ull a2 = pk2(sA[kk][ty * 4 + r]);
                fma2(acc[r][0], a2, b01.x);
                fma2(acc[r][1], a2, b01.y);
            }
        }
        __syncthreads();
    }
#pragma unroll
    for (int r = 0; r < 4; r++) {
        int m = m0 + ty * 4 + r, o = n0 + tx * 4;
        float2 lo = upk(acc[r][0]), hi = upk(acc[r][1]);
        *(float4*)(g_part[blockIdx.z] + (size_t)m * OUTD + o) =
            make_float4(lo.x, lo.y, hi.x, hi.y);
    }
}

__global__ void k5r_reduce(const float* __restrict__ out_b, float* __restrict__ out) {
    int idx = blockIdx.x * 256 + threadIdx.x;
    if (idx < NRES * OUTD) {
        out[idx] = g_part[0][idx] + g_part[1][idx] + g_part[2][idx] + out_b[idx % OUTD];
    }
}

// ---------------- launch ----------------------------------------------------
extern "C" void kernel_launch(void* const* d_in, const int* in_sizes, int n_in,
                              void* d_out, int out_size) {
    const float* in1d  = (const float*)d_in[0];
    const float* in2d  = (const float*)d_in[1];
    const float* rot   = (const float*)d_in[2];
    const float* trans = (const float*)d_in[3];
    const float* qw    = (const float*)d_in[4];
    const float* qb    = (const float*)d_in[5];
    const float* kvw   = (const float*)d_in[6];
    const float* kvb   = (const float*)d_in[7];
    const float* qpw   = (const float*)d_in[8];
    const float* qpb   = (const float*)d_in[9];
    const float* kvpw  = (const float*)d_in[10];
    const float* kvpb  = (const float*)d_in[11];
    const float* tpw   = (const float*)d_in[12];
    const float* w2d   = (const float*)d_in[13];
    const float* b2d   = (const float*)d_in[14];
    const float* ow    = (const float*)d_in[15];
    const float* ob    = (const float*)d_in[16];
    float* out = (float*)d_out;

    cudaFuncSetAttribute(k2_a2d, cudaFuncAttributeMaxDynamicSharedMemorySize, K2_SMEM);
    cudaFuncSetAttribute(k4a_aover, cudaFuncAttributeMaxDynamicSharedMemorySize, K4A_SMEM);

    k0_prep<<<1728, 256>>>(qw, qb, kvw, kvb, qpw, qpb, kvpw, kvpb, tpw);
    k1a_gemm<<<dim3(18, 12), 256>>>(in1d);
    k1b_pack<<<768, 256>>>(rot, trans);
    k2_a2d<<<2304, 256, K2_SMEM>>>(in2d, w2d, b2d);
    k3_softmax<<<dim3(96, 12), 256>>>();
    k4a_aover<<<768, 256, K4A_SMEM>>>(in2d);
    k4b_vattend<<<dim3(12, 12), 320>>>(rot, trans);
    k5_out<<<dim3(6, 12, 3), 256>>>(ow);
    k5r_reduce<<<1152, 256>>>(ob, out);
}

// round 12
// speedup vs baseline: 2.1986x; 1.0165x over previous
#include <cuda_runtime.h>
#include <math.h>

#define NRES 768
#define MSAD 384
#define NH 12
#define PAIRD 128
#define OUTD 384
#define PROJ 1152
#define FINALD 2112

typedef unsigned long long ull;

// ---------------- f32x2 helpers (Blackwell packed fp32) ---------------------
__device__ __forceinline__ ull pk2(float v) {
    ull r; asm("mov.b64 %0, {%1, %1};" : "=l"(r) : "f"(v)); return r;
}
__device__ __forceinline__ ull pk2two(float lo, float hi) {
    ull r; asm("mov.b64 %0, {%1, %2};" : "=l"(r) : "f"(lo), "f"(hi)); return r;
}
__device__ __forceinline__ void fma2(ull& d, ull a, ull b) {
    asm("fma.rn.f32x2 %0, %1, %2, %0;" : "+l"(d) : "l"(a), "l"(b));
}
__device__ __forceinline__ void add2(ull& d, ull b) {
    asm("add.rn.f32x2 %0, %0, %1;" : "+l"(d) : "l"(b));
}
__device__ __forceinline__ float2 upk(ull v) {
    float2 r; asm("mov.b64 {%0, %1}, %2;" : "=f"(r.x), "=f"(r.y) : "l"(v)); return r;
}
// ---------------- cp.async helpers ------------------------------------------
__device__ __forceinline__ void cp16(void* dst, const void* src) {
    unsigned d = (unsigned)__cvta_generic_to_shared(dst);
    asm volatile("cp.async.cg.shared.global [%0], [%1], 16;" :: "r"(d), "l"(src));
}
__device__ __forceinline__ void cp_commit() {
    asm volatile("cp.async.commit_group;" ::: "memory");
}
__device__ __forceinline__ void cp_wait2() {
    asm volatile("cp.async.wait_group 2;" ::: "memory");
}

// ---------------- scratch (device globals; no allocation allowed) ----------
__device__ float g_proj[NRES * PROJ];
__device__ float g_qpack[NH * NRES * 28];
__device__ float g_kpackT[NH * 32 * NRES];  // [h][d][j], d-major (d28 = bias)
__device__ float g_vpack2[NH * NRES * 40];
__device__ float g_logits[NH * NRES * NRES]; // a2d (k2) -> attn (k3)
__device__ float g_final[NRES * FINALD];
__device__ float g_part[3][NRES * OUTD];

// ---------------- K1a: projection GEMM 768x1152x384 (f32x2) -----------------
// Weight concat folded into the staging loads (no k0 prepass). Region
// boundaries 192/576/720 are even, n-tiles are 64-aligned, so float2 loads
// never straddle regions.
__global__ __launch_bounds__(256) void k1a_gemm(const float* __restrict__ in1d,
                                                const float* __restrict__ qw,  const float* __restrict__ qb,
                                                const float* __restrict__ kvw, const float* __restrict__ kvb,
                                                const float* __restrict__ qpw, const float* __restrict__ qpb,
                                                const float* __restrict__ kvpw,const float* __restrict__ kvpb) {
    __shared__ float sA[32][65];
    __shared__ ull sB2[32][32];
    int tid = threadIdx.x;
    int tx = tid & 15, ty = tid >> 4;
    int m0 = blockIdx.y * 64, n0 = blockIdx.x * 64;
    ull acc[4][2] = {};
    for (int k0 = 0; k0 < MSAD; k0 += 32) {
        for (int idx = tid; idx < 64 * 32; idx += 256) {
            int m = idx >> 5, kk = idx & 31;
            sA[kk][m] = in1d[(m0 + m) * MSAD + k0 + kk];
        }
        for (int idx = tid; idx < 32 * 32; idx += 256) {
            int kk = idx >> 5, op = idx & 31;
            int o = n0 + op * 2, k = k0 + kk;
            float2 w;
            if (o < 192)      w = *(const float2*)(qw + k * 192 + o);
            else if (o < 576) w = *(const float2*)(kvw + k * 384 + (o - 192));
            else if (o < 720) w = *(const float2*)(qpw + k * 144 + (o - 576));
            else              w = *(const float2*)(kvpw + k * 432 + (o - 720));
            sB2[kk][op] = pk2two(w.x, w.y);
        }
        __syncthreads();
#pragma unroll
        for (int kk = 0; kk < 32; kk++) {
            ulonglong2 b01 = *(const ulonglong2*)&sB2[kk][tx * 2];
#pragma unroll
            for (int r = 0; r < 4; r++) {
                ull a2 = pk2(sA[kk][ty * 4 + r]);
                fma2(acc[r][0], a2, b01.x);
                fma2(acc[r][1], a2, b01.y);
            }
        }
        __syncthreads();
    }
#pragma unroll
    for (int r = 0; r < 4; r++) {
        int m = m0 + ty * 4 + r, o = n0 + tx * 4;
        float2 lo = upk(acc[r][0]), hi = upk(acc[r][1]);
        float vv[4] = { lo.x, lo.y, hi.x, hi.y };
#pragma unroll
        for (int q = 0; q < 4; q++) {
            int oo = o + q;
            float b;
            if (oo < 192)      b = qb[oo];
            else if (oo < 576) b = kvb[oo - 192];
            else if (oo < 720) b = qpb[oo - 576];
            else               b = kvpb[oo - 720];
            g_proj[(size_t)m * PROJ + oo] = vv[q] + b;
        }
    }
}

// ---------------- K1b: apply rotations, pack q/k/v --------------------------
__global__ __launch_bounds__(256) void k1b_pack(const float* __restrict__ rot,
                                                const float* __restrict__ trans,
                                                const float* __restrict__ tpw) {
    __shared__ float sp[PROJ];
    __shared__ float srot[9], strans[3], spw[12];
    __shared__ float sg[192 * 3];
    int n = blockIdx.x, tid = threadIdx.x;
    for (int t = tid; t < PROJ; t += 256) sp[t] = g_proj[n * PROJ + t];
    if (tid < 9) srot[tid] = rot[n * 9 + tid];
    if (tid < 3) strans[tid] = trans[n * 3 + tid];
    if (tid < 12) {
        float x = tpw[tid];
        float sf = (x > 20.f) ? x : log1pf(__expf(x));
        spw[tid] = sf * 0.13608276348795434f; // sqrt(1/54)
    }
    __syncthreads();

    if (tid < 192) {
        int h = tid >> 4, d = tid & 15;
        g_qpack[(h * NRES + n) * 28 + d] = sp[tid] * 0.14433756729740643f; // 1/sqrt(48)
    }
    for (int t = tid; t < 384; t += 256) {
        int h = t >> 5, d = t & 31;
        if (d < 16) g_kpackT[((size_t)h * 32 + d) * NRES + n] = sp[192 + t];
        else        g_vpack2[((size_t)h * NRES + n) * 40 + (d - 16)] = sp[192 + t];
    }
    if (tid < 192) {
        float l0, l1, l2;
        if (tid < 48) { l0 = sp[576 + tid]; l1 = sp[576 + 48 + tid]; l2 = sp[576 + 96 + tid]; }
        else { int vs = tid - 48; l0 = sp[720 + vs]; l1 = sp[720 + 144 + vs]; l2 = sp[720 + 288 + vs]; }
#pragma unroll
        for (int c = 0; c < 3; c++)
            sg[tid * 3 + c] = srot[c * 3 + 0] * l0 + srot[c * 3 + 1] * l1 + srot[c * 3 + 2] * l2 + strans[c];
    }
    __syncthreads();
    if (tid < 48) {
        int h = tid >> 2, p = tid & 3;
        float pw = spw[h];
#pragma unroll
        for (int c = 0; c < 3; c++)
            g_qpack[(h * NRES + n) * 28 + 16 + p * 3 + c] = pw * sg[tid * 3 + c];
    } else if (tid < 192) {
        int vs = tid - 48, h = vs / 12, s = vs % 12;
        if (s < 4) {
#pragma unroll
            for (int c = 0; c < 3; c++)
                g_kpackT[((size_t)h * 32 + 16 + s * 3 + c) * NRES + n] = sg[tid * 3 + c];
        } else {
#pragma unroll
            for (int c = 0; c < 3; c++)
                g_vpack2[((size_t)h * NRES + n) * 40 + 16 + (s - 4) * 3 + c] = sg[tid * 3 + c];
        }
    }
    if (tid >= 192 && tid < 204) {
        int h = tid - 192;
        float s2 = 0.f;
        for (int s = 0; s < 4; s++)
            for (int c = 0; c < 3; c++) {
                float v = sg[(48 + h * 12 + s) * 3 + c];
                s2 += v * v;
            }
        g_kpackT[((size_t)h * 32 + 28) * NRES + n] = -0.5f * spw[h] * s2;
    }
}

// ---------------- K2: a2d GEMM, cp.async 3-buffer, 128-thr (6 blk/SM) -------
// Stage = 128 rows x 16 cols, pitch 20 (80B rows, 16B-aligned, LDS.128-safe).
// smem: sbuf [3][128*20] @0 (30720), sw2 @30720 (6144), sb @36864
#define K2_SMEM 36928
__global__ __launch_bounds__(128) void k2_a2d(const float* __restrict__ in2d,
                                              const float* __restrict__ w2d,
                                              const float* __restrict__ b2d) {
    extern __shared__ char smraw[];
    float* sbuf = (float*)smraw;
    ull*   sw2  = (ull*)(smraw + 30720);
    float* sb   = (float*)(smraw + 36864);
    int tid = threadIdx.x;
    size_t p0 = (size_t)blockIdx.x * 128;
    const float* src = in2d + p0 * PAIRD;

    // prologue: issue chunks 0 and 1
#pragma unroll
    for (int s = 0; s < 2; s++) {
#pragma unroll
        for (int t = 0; t < 4; t++) {
            int f = tid + t * 128;          // 0..511
            int r = f >> 2, c4 = f & 3;
            cp16(sbuf + s * 2560 + r * 20 + c4 * 4,
                 src + (size_t)r * PAIRD + s * 16 + c4 * 4);
        }
        cp_commit();
    }
    // stage weights (overlaps with in-flight cp.async)
    for (int f = tid; f < 128 * 6; f += 128) {
        int c = f / 6, hp = f % 6;
        float2 w = *(const float2*)(w2d + c * 12 + hp * 2);
        sw2[f] = pk2two(w.x, w.y);
    }
    if (tid < 12) sb[tid] = b2d[tid];

    ull acc[6] = {};
#pragma unroll
    for (int ck = 0; ck < 8; ck++) {
        if (ck + 2 < 8) {
            int sn = ck + 2;
#pragma unroll
            for (int t = 0; t < 4; t++) {
                int f = tid + t * 128;
                int r = f >> 2, c4 = f & 3;
                cp16(sbuf + (sn % 3) * 2560 + r * 20 + c4 * 4,
                     src + (size_t)r * PAIRD + sn * 16 + c4 * 4);
            }
        }
        cp_commit();
        cp_wait2();
        __syncthreads();
        const float4* A4 = (const float4*)&sbuf[(ck % 3) * 2560 + tid * 20];
#pragma unroll
        for (int k4 = 0; k4 < 4; k4++) {
            float4 a = A4[k4];
#pragma unroll
            for (int q = 0; q < 4; q++) {
                float av = (q == 0) ? a.x : (q == 1) ? a.y : (q == 2) ? a.z : a.w;
                ull a2 = pk2(av);
                const ull* w = &sw2[(ck * 16 + k4 * 4 + q) * 6];
                ulonglong2 w01 = *(const ulonglong2*)(w + 0);
                ulonglong2 w23 = *(const ulonglong2*)(w + 2);
                ulonglong2 w45 = *(const ulonglong2*)(w + 4);
                fma2(acc[0], a2, w01.x); fma2(acc[1], a2, w01.y);
                fma2(acc[2], a2, w23.x); fma2(acc[3], a2, w23.y);
                fma2(acc[4], a2, w45.x); fma2(acc[5], a2, w45.y);
            }
        }
        __syncthreads();
    }
    size_t p = p0 + tid;
    int i = (int)(p / NRES), j = (int)(p % NRES);
    float res[12];
#pragma unroll
    for (int hp = 0; hp < 6; hp++) {
        float2 v = upk(acc[hp]);
        res[2 * hp] = v.x; res[2 * hp + 1] = v.y;
    }
#pragma unroll
    for (int h = 0; h < 12; h++)
        g_logits[((size_t)h * NRES + i) * NRES + j] = (res[h] + sb[h]) * 0.5773502691896258f;
}

// ---------------- K3: qk logits (coalesced kpackT) + softmax ----------------
__global__ __launch_bounds__(256) void k3_softmax() {
    __shared__ float srow[8][NRES];
    __shared__ ull su2[8][14];
    int h = blockIdx.y, i0 = blockIdx.x * 8;
    int tid = threadIdx.x;
    for (int t = tid; t < 8 * 14; t += 256) {
        int i8 = t / 14, dp = t % 14;
        const float* qp = g_qpack + ((size_t)h * NRES + (i0 + i8)) * 28 + dp * 2;
        su2[i8][dp] = pk2two(qp[0], qp[1]);
    }
    __syncthreads();
    const float* kbase = g_kpackT + (size_t)h * 32 * NRES;
    for (int jj = 0; jj < 3; jj++) {
        int j = jj * 256 + tid;
        const float* kb = kbase + j;
        ull wr2[14];
#pragma unroll
        for (int dp = 0; dp < 14; dp++)
            wr2[dp] = pk2two(__ldg(kb + (size_t)(2 * dp) * NRES),
                             __ldg(kb + (size_t)(2 * dp + 1) * NRES));
        float bias = __ldg(kb + (size_t)28 * NRES);
#pragma unroll
        for (int i8 = 0; i8 < 8; i8++) {
            ull acc2 = 0;
#pragma unroll
            for (int dp = 0; dp < 14; dp++) fma2(acc2, su2[i8][dp], wr2[dp]);
            float2 t = upk(acc2);
            srow[i8][j] = t.x + t.y + bias
                        + g_logits[((size_t)h * NRES + (i0 + i8)) * NRES + j];
        }
    }
    __syncthreads();
    int w = tid >> 5, lane = tid & 31;
    float vals[24];
    float m = -1e30f;
#pragma unroll
    for (int t = 0; t < 24; t++) {
        vals[t] = srow[w][t * 32 + lane];
        m = fmaxf(m, vals[t]);
    }
#pragma unroll
    for (int o = 16; o > 0; o >>= 1) m = fmaxf(m, __shfl_xor_sync(~0u, m, o));
    float s = 0.f;
#pragma unroll
    for (int t = 0; t < 24; t++) {
        float e = __expf(vals[t] - m);
        vals[t] = e; s += e;
    }
#pragma unroll
    for (int o = 16; o > 0; o >>= 1) s += __shfl_xor_sync(~0u, s, o);
    float inv = 1.f / s;
    float* dst = g_logits + ((size_t)h * NRES + (i0 + w)) * NRES;
#pragma unroll
    for (int t = 0; t < 24; t++) dst[t * 32 + lane] = vals[t] * inv;
}

// ---------------- K4a: a_over_2d (cp.async; each element read once) ---------
// smem: sattnT float[768*12] @0 (36864), sbuf float[4][16*128] @36864 (32768)
#define K4A_SMEM 69632
__global__ __launch_bounds__(256) void k4a_aover(const float* __restrict__ in2d) {
    extern __shared__ char smraw[];
    float* sattnT = (float*)smraw;            // [j][12]
    float* sbuf   = (float*)(smraw + 36864);
    int i = blockIdx.x, tid = threadIdx.x;

    const float* src = in2d + (size_t)i * NRES * PAIRD;
#pragma unroll
    for (int s = 0; s < 3; s++) {
#pragma unroll
        for (int t = 0; t < 2; t++) {
            int f = tid + t * 256;
            int r = f >> 5, c4 = f & 31;
            cp16(sbuf + s * 2048 + r * 128 + c4 * 4,
                 src + (size_t)(s * 16 + r) * PAIRD + c4 * 4);
        }
        cp_commit();
    }
    for (int f = tid; f < 9216; f += 256) {
        int h = f / NRES, j = f % NRES;
        sattnT[j * 12 + h] = __ldg(g_logits + ((size_t)h * NRES + i) * NRES + j);
    }
    __syncthreads();

    int rg = tid >> 6, cp = tid & 63;
    ull acc[12] = {};

    for (int s = 0; s < 48; s++) {
        cp_wait2();
        __syncthreads();
        if (s + 3 < 48) {
            int sn = s + 3;
#pragma unroll
            for (int t = 0; t < 2; t++) {
                int f = tid + t * 256;
                int r = f >> 5, c4 = f & 31;
                cp16(sbuf + (sn & 3) * 2048 + r * 128 + c4 * 4,
                     src + (size_t)(sn * 16 + r) * PAIRD + c4 * 4);
            }
        }
        cp_commit();
        const ull* bb = (const ull*)(sbuf + (s & 3) * 2048);
        int j0 = s * 16;
#pragma unroll
        for (int r = 0; r < 4; r++) {
            int jl = rg * 4 + r;
            ull d = bb[jl * 64 + cp];
            const float4* ap = (const float4*)&sattnT[(j0 + jl) * 12];
            float4 a0 = ap[0], a1 = ap[1], a2v = ap[2];
            fma2(acc[0], pk2(a0.x), d);  fma2(acc[1], pk2(a0.y), d);
            fma2(acc[2], pk2(a0.z), d);  fma2(acc[3], pk2(a0.w), d);
            fma2(acc[4], pk2(a1.x), d);  fma2(acc[5], pk2(a1.y), d);
            fma2(acc[6], pk2(a1.z), d);  fma2(acc[7], pk2(a1.w), d);
            fma2(acc[8], pk2(a2v.x), d); fma2(acc[9], pk2(a2v.y), d);
            fma2(acc[10], pk2(a2v.z), d); fma2(acc[11], pk2(a2v.w), d);
        }
    }
    __syncthreads();
    ull* red = (ull*)sbuf;   // [256][13] ull = 26624 B <= 32768
#pragma unroll
    for (int h = 0; h < 12; h++) red[(rg * 64 + cp) * 13 + h] = acc[h];
    __syncthreads();
    for (int pi = tid; pi < 768; pi += 256) {
        int h = pi >> 6, c2 = pi & 63;
        ull t0 = red[(0 * 64 + c2) * 13 + h];
        add2(t0, red[(1 * 64 + c2) * 13 + h]);
        add2(t0, red[(2 * 64 + c2) * 13 + h]);
        add2(t0, red[(3 * 64 + c2) * 13 + h]);
        float2 v = upk(t0);
        *(float2*)(g_final + (size_t)i * FINALD + 576 + h * PAIRD + 2 * c2) = v;
    }
}

// ---------------- K4b: per-head GEMM for v / vp + rotate-back epilogue ------
__global__ __launch_bounds__(320) void k4b_vattend(const float* __restrict__ rot,
                                                   const float* __restrict__ trans) {
    __shared__ float2 sattn2[64][65];
    __shared__ ull svp[64 * 20];
    __shared__ float srpg[64][24];
    int i0 = blockIdx.x * 64, h = blockIdx.y;
    int tid = threadIdx.x, il = tid & 63, dg = tid >> 6;
    ull acc[4] = {};
    for (int j0 = 0; j0 < NRES; j0 += 64) {
        for (int f = tid; f < 4096; f += 320) {
            int r = f >> 6, c = f & 63;
            float a = g_logits[((size_t)h * NRES + i0 + r) * NRES + j0 + c];
            sattn2[r][c] = make_float2(a, a);
        }
        for (int f = tid; f < 1280; f += 320)
            svp[f] = __ldg((const ull*)(g_vpack2 + ((size_t)h * NRES + j0) * 40) + f);
        __syncthreads();
#pragma unroll 4
        for (int jj = 0; jj < 64; jj++) {
            ull a2 = *(const ull*)&sattn2[il][jj];
            const ulonglong2* wv = (const ulonglong2*)&svp[jj * 20 + dg * 4];
            ulonglong2 w01 = wv[0], w23 = wv[1];
            fma2(acc[0], a2, w01.x); fma2(acc[1], a2, w01.y);
            fma2(acc[2], a2, w23.x); fma2(acc[3], a2, w23.y);
        }
        __syncthreads();
    }
    int n_i = i0 + il;
    float v[8];
#pragma unroll
    for (int q = 0; q < 4; q++) {
        float2 t = upk(acc[q]);
        v[2 * q] = t.x; v[2 * q + 1] = t.y;
    }
    if (dg < 2) {
        float* dst = g_final + (size_t)n_i * FINALD + h * 16 + dg * 8;
#pragma unroll
        for (int t = 0; t < 8; t++) dst[t] = v[t];
    } else {
        int d0 = (dg - 2) * 8;
#pragma unroll
        for (int t = 0; t < 8; t++) srpg[il][d0 + t] = v[t];
    }
    __syncthreads();
    for (int f = tid; f < 512; f += 320) {
        int ii = f >> 3, p = f & 7;
        int n = i0 + ii;
        float vx = srpg[ii][p * 3 + 0] - trans[n * 3 + 0];
        float vy = srpg[ii][p * 3 + 1] - trans[n * 3 + 1];
        float vz = srpg[ii][p * 3 + 2] - trans[n * 3 + 2];
        float nn = 1e-8f;
#pragma unroll
        for (int ic = 0; ic < 3; ic++) {
            float rl = rot[n * 9 + 0 + ic] * vx + rot[n * 9 + 3 + ic] * vy + rot[n * 9 + 6 + ic] * vz;
            g_final[(size_t)n * FINALD + 192 + ic * 96 + h * 8 + p] = rl;
            nn += rl * rl;
        }
        g_final[(size_t)n * FINALD + 480 + h * 8 + p] = sqrtf(nn);
    }
}

// ---------------- K5: output GEMM 768x384, K=2112, split-K=3 (f32x2) --------
__global__ __launch_bounds__(256) void k5_out(const float* __restrict__ out_w) {
    __shared__ float sA[32][65];
    __shared__ ull sB2[32][32];
    int tid = threadIdx.x, tx = tid & 15, ty = tid >> 4;
    int m0 = blockIdx.y * 64, n0 = blockIdx.x * 64;
    int kb = blockIdx.z * 704;
    ull acc[4][2] = {};
    for (int k0 = kb; k0 < kb + 704; k0 += 32) {
        for (int idx = tid; idx < 64 * 32; idx += 256) {
            int m = idx >> 5, kk = idx & 31;
            sA[kk][m] = g_final[(size_t)(m0 + m) * FINALD + k0 + kk];
        }
        for (int idx = tid; idx < 32 * 32; idx += 256) {
            int kk = idx >> 5, op = idx & 31;
            float2 wv = *(const float2*)(out_w + (size_t)(k0 + kk) * OUTD + n0 + op * 2);
            sB2[kk][op] = pk2two(wv.x, wv.y);
        }
        __syncthreads();
#pragma unroll
        for (int kk = 0; kk < 32; kk++) {
            ulonglong2 b01 = *(const ulonglong2*)&sB2[kk][tx * 2];
#pragma unroll
            for (int r = 0; r < 4; r++) {
                ull a2 = pk2(sA[kk][ty * 4 + r]);
                fma2(acc[r][0], a2, b01.x);
                fma2(acc[r][1], a2, b01.y);
            }
        }
        __syncthreads();
    }
#pragma unroll
    for (int r = 0; r < 4; r++) {
        int m = m0 + ty * 4 + r, o = n0 + tx * 4;
        float2 lo = upk(acc[r][0]), hi = upk(acc[r][1]);
        *(float4*)(g_part[blockIdx.z] + (size_t)m * OUTD + o) =
            make_float4(lo.x, lo.y, hi.x, hi.y);
    }
}

__global__ void k5r_reduce(const float* __restrict__ out_b, float* __restrict__ out) {
    int idx = blockIdx.x * 256 + threadIdx.x;
    if (idx < NRES * OUTD) {
        out[idx] = g_part[0][idx] + g_part[1][idx] + g_part[2][idx] + out_b[idx % OUTD];
    }
}

// ---------------- launch ----------------------------------------------------
extern "C" void kernel_launch(void* const* d_in, const int* in_sizes, int n_in,
                              void* d_out, int out_size) {
    const float* in1d  = (const float*)d_in[0];
    const float* in2d  = (const float*)d_in[1];
    const float* rot   = (const float*)d_in[2];
    const float* trans = (const float*)d_in[3];
    const float* qw    = (const float*)d_in[4];
    const float* qb    = (const float*)d_in[5];
    const float* kvw   = (const float*)d_in[6];
    const float* kvb   = (const float*)d_in[7];
    const float* qpw   = (const float*)d_in[8];
    const float* qpb   = (const float*)d_in[9];
    const float* kvpw  = (const float*)d_in[10];
    const float* kvpb  = (const float*)d_in[11];
    const float* tpw   = (const float*)d_in[12];
    const float* w2d   = (const float*)d_in[13];
    const float* b2d   = (const float*)d_in[14];
    const float* ow    = (const float*)d_in[15];
    const float* ob    = (const float*)d_in[16];
    float* out = (float*)d_out;

    cudaFuncSetAttribute(k2_a2d, cudaFuncAttributeMaxDynamicSharedMemorySize, K2_SMEM);
    cudaFuncSetAttribute(k4a_aover, cudaFuncAttributeMaxDynamicSharedMemorySize, K4A_SMEM);

    k1a_gemm<<<dim3(18, 12), 256>>>(in1d, qw, qb, kvw, kvb, qpw, qpb, kvpw, kvpb);
    k1b_pack<<<768, 256>>>(rot, trans, tpw);
    k2_a2d<<<4608, 128, K2_SMEM>>>(in2d, w2d, b2d);
    k3_softmax<<<dim3(96, 12), 256>>>();
    k4a_aover<<<768, 256, K4A_SMEM>>>(in2d);
    k4b_vattend<<<dim3(12, 12), 320>>>(rot, trans);
    k5_out<<<dim3(6, 12, 3), 256>>>(ow);
    k5r_reduce<<<1152, 256>>>(ob, out);
}